// round 6
// baseline (speedup 1.0000x reference)
#include <cuda_runtime.h>
#include <math.h>
#include <stdint.h>

// Problem constants
#define BATCH 2
#define SQ    2048
#define DM    2048     // model dim
#define KVD   512      // G*HD
#define NH    32       // heads
#define HDIM  64       // head dim

// Scratch (allocation-free rule: __device__ globals)
__device__ float g_Q[(size_t)BATCH * SQ * DM];   // tf32-rounded
__device__ float g_K[(size_t)BATCH * SQ * KVD];  // tf32-rounded
__device__ float g_V[(size_t)BATCH * SQ * KVD];  // tf32-rounded
__device__ float g_C[(size_t)BATCH * SQ * DM];   // ctx, tf32-rounded
__device__ float g_Xt[(size_t)BATCH * SQ * DM];  // x, tf32-rounded
// packed tf32 weights: Wq | Wk | Wv | Wo
#define WQ_OFF 0
#define WK_OFF (2048 * 2048)
#define WV_OFF (WK_OFF + 512 * 2048)
#define WO_OFF (WV_OFF + 512 * 2048)
__device__ float g_Wt[WO_OFF + 2048 * 2048];

// ---------------------------------------------------------------------------
// helpers
// ---------------------------------------------------------------------------
__device__ __forceinline__ uint32_t smem_u32(const void* p) {
    uint32_t a;
    asm("{ .reg .u64 t; cvta.to.shared.u64 t, %1; cvt.u32.u64 %0, t; }"
        : "=r"(a) : "l"(p));
    return a;
}
__device__ __forceinline__ void cp_async16(uint32_t dst, const void* src) {
    asm volatile("cp.async.cg.shared.global [%0], [%1], 16;" :: "r"(dst), "l"(src));
}
__device__ __forceinline__ void cp_commit() {
    asm volatile("cp.async.commit_group;" ::: "memory");
}
template <int N>
__device__ __forceinline__ void cp_wait() {
    asm volatile("cp.async.wait_group %0;" :: "n"(N) : "memory");
}
__device__ __forceinline__ uint32_t f2tf32(float f) {
    uint32_t r;
    asm("cvt.rna.tf32.f32 %0, %1;" : "=r"(r) : "f"(f));
    return r;
}
__device__ __forceinline__ float f2tf32f(float f) {
    return __uint_as_float(f2tf32(f));
}
__device__ __forceinline__ void mma_tf32(float* c, const uint32_t* a, const uint32_t* b) {
    asm volatile(
        "mma.sync.aligned.m16n8k8.row.col.f32.tf32.tf32.f32 "
        "{%0,%1,%2,%3}, {%4,%5,%6,%7}, {%8,%9}, {%0,%1,%2,%3};"
        : "+f"(c[0]), "+f"(c[1]), "+f"(c[2]), "+f"(c[3])
        : "r"(a[0]), "r"(a[1]), "r"(a[2]), "r"(a[3]), "r"(b[0]), "r"(b[1]));
}

// ---------------------------------------------------------------------------
// One-shot fp32 -> tf32-bits conversion (bandwidth kernel)
// ---------------------------------------------------------------------------
__global__ __launch_bounds__(256) void cvt_tf32_k(const float4* __restrict__ src,
                                                  float4* __restrict__ dst, int n4)
{
    int i = blockIdx.x * 256 + threadIdx.x;
    if (i < n4) {
        float4 v = src[i];
        dst[i] = make_float4(f2tf32f(v.x), f2tf32f(v.y), f2tf32f(v.z), f2tf32f(v.w));
    }
}

// ---------------------------------------------------------------------------
// TF32 mma.sync GEMM on pre-converted data:  C[M,N] = A[M,K] . W[N,K]^T
// CTA: 128x128 tile, BK=32, 128 threads (4 warps, 2x2; warp tile 64x64).
// cp.async double-buffered smem. Epilogue rounds to tf32 for csel 0/1/2.
// ---------------------------------------------------------------------------
#define ASTRIDE 36
#define STG_FLT (2 * 128 * ASTRIDE)         // floats per stage (A + B) = 9216
#define GEMM_SMEM (2 * STG_FLT * 4)         // 73728 bytes

__global__ __launch_bounds__(128) void gemm_tc32(
    int asel, int woff, int csel, float* __restrict__ Cext,
    int M, int N, int K)
{
    extern __shared__ float sm[];
    const uint32_t sb = smem_u32(sm);
    const float* A = asel ? g_C : g_Xt;
    const float* W = g_Wt + woff;
    float* C = (csel == 0) ? g_Q : (csel == 1) ? g_K : (csel == 2) ? g_V : Cext;

    const int tid = threadIdx.x;
    const int wid = tid >> 5;
    const int lane = tid & 31;
    const int m0 = blockIdx.y * 128;
    const int n0 = blockIdx.x * 128;
    const int wm0 = (wid >> 1) * 64;
    const int wn0 = (wid & 1) * 64;

    float c[4][8][4];
#pragma unroll
    for (int mt = 0; mt < 4; mt++)
#pragma unroll
        for (int nt = 0; nt < 8; nt++)
#pragma unroll
            for (int i = 0; i < 4; i++) c[mt][nt][i] = 0.f;

    const int nk = K / 32;

    auto issue = [&](int kt) {
        const int buf = kt & 1;
        const uint32_t abase = sb + buf * STG_FLT * 4;
        const uint32_t bbase = abase + 128 * ASTRIDE * 4;
        const int k0 = kt * 32;
#pragma unroll
        for (int i = 0; i < 8; i++) {
            int idx = tid + i * 128;            // 0..1023
            int row = idx >> 3;
            int ch = idx & 7;
            cp_async16(abase + (row * ASTRIDE + ch * 4) * 4,
                       &A[(size_t)(m0 + row) * K + k0 + ch * 4]);
            cp_async16(bbase + (row * ASTRIDE + ch * 4) * 4,
                       &W[(size_t)(n0 + row) * K + k0 + ch * 4]);
        }
        cp_commit();
    };

    issue(0);

    for (int kt = 0; kt < nk; kt++) {
        if (kt + 1 < nk) {
            issue(kt + 1);
            cp_wait<1>();
        } else {
            cp_wait<0>();
        }
        __syncthreads();

        const float* As = sm + (kt & 1) * STG_FLT;
        const float* Bs = As + 128 * ASTRIDE;

#pragma unroll
        for (int ks = 0; ks < 4; ks++) {
            const int kk = ks * 8 + (lane & 3);
            uint32_t a[4][4], b[8][2];
            const float* ap = As + (wm0 + (lane >> 2)) * ASTRIDE + kk;
#pragma unroll
            for (int mt = 0; mt < 4; mt++) {
                const float* p = ap + mt * 16 * ASTRIDE;
                a[mt][0] = __float_as_uint(p[0]);
                a[mt][1] = __float_as_uint(p[8 * ASTRIDE]);
                a[mt][2] = __float_as_uint(p[4]);
                a[mt][3] = __float_as_uint(p[8 * ASTRIDE + 4]);
            }
            const float* bp = Bs + (wn0 + (lane >> 2)) * ASTRIDE + kk;
#pragma unroll
            for (int nt = 0; nt < 8; nt++) {
                b[nt][0] = __float_as_uint(bp[nt * 8 * ASTRIDE]);
                b[nt][1] = __float_as_uint(bp[nt * 8 * ASTRIDE + 4]);
            }
#pragma unroll
            for (int mt = 0; mt < 4; mt++)
#pragma unroll
                for (int nt = 0; nt < 8; nt++)
                    mma_tf32(c[mt][nt], a[mt], b[nt]);
        }
        __syncthreads();
    }

    const bool rnd = (csel != 3);
#pragma unroll
    for (int mt = 0; mt < 4; mt++) {
        const int r0 = m0 + wm0 + mt * 16 + (lane >> 2);
#pragma unroll
        for (int nt = 0; nt < 8; nt++) {
            const int col = n0 + wn0 + nt * 8 + (lane & 3) * 2;
            float v0 = c[mt][nt][0], v1 = c[mt][nt][1];
            float v2 = c[mt][nt][2], v3 = c[mt][nt][3];
            if (rnd) {
                v0 = f2tf32f(v0); v1 = f2tf32f(v1);
                v2 = f2tf32f(v2); v3 = f2tf32f(v3);
            }
            *(float2*)&C[(size_t)r0 * N + col] = make_float2(v0, v1);
            *(float2*)&C[(size_t)(r0 + 8) * N + col] = make_float2(v2, v3);
        }
    }
}

// ---------------------------------------------------------------------------
// Tensor-core causal GQA flash attention (tf32 mma, fp32 softmax).
// CTA: (qt, b*32+h); 256 threads = 8 warps; BQ=128 (16 q-rows/warp), BKV=64.
// Q/K/V arrive pre-rounded to tf32 (GEMM epilogue) -> loads are pure copies.
// ---------------------------------------------------------------------------
#define PAD 68
#define ATTN_SMEM ((64 * PAD + 64 * PAD + 128 * PAD) * 4)   // 69632 B

__global__ __launch_bounds__(256, 2) void gqa_attn_tc()
{
    extern __shared__ float asm_[];
    float* Ks = asm_;                 // [64][PAD]
    float* Vt = Ks + 64 * PAD;        // [64][PAD]
    float* Pt = Vt + 64 * PAD;        // [128][PAD]

    const int tid = threadIdx.x;
    const int w = tid >> 5;
    const int lane = tid & 31;
    const int r = lane >> 2;
    const int cb = lane & 3;
    const int qt = blockIdx.x;
    const int bh = blockIdx.y;
    const int b = bh >> 5, h = bh & 31, g = h >> 2;
    const int q0 = qt * 128;
    const int wrow = w * 16;
    const int sw = (r & 3) << 3;

    const float* Qb = g_Q + (size_t)b * SQ * DM + h * HDIM;
    const float* Kb = g_K + (size_t)b * SQ * KVD + g * HDIM;
    const float* Vb = g_V + (size_t)b * SQ * KVD + g * HDIM;

    // Stage Q (x 0.125 exact; inputs already tf32-rounded) into Pt
#pragma unroll
    for (int i = 0; i < 8; i++) {
        int idx = tid + i * 256;
        int row = idx >> 4, ch = idx & 15;
        float4 v = *(const float4*)&Qb[(size_t)(q0 + row) * DM + ch * 4];
        float* dst = &Pt[row * PAD + ch * 4];
        dst[0] = v.x * 0.125f;
        dst[1] = v.y * 0.125f;
        dst[2] = v.z * 0.125f;
        dst[3] = v.w * 0.125f;
    }
    __syncthreads();

    uint32_t qf[8][4];
#pragma unroll
    for (int ks = 0; ks < 8; ks++) {
        qf[ks][0] = __float_as_uint(Pt[(wrow + r) * PAD + ks * 8 + cb]);
        qf[ks][1] = __float_as_uint(Pt[(wrow + 8 + r) * PAD + ks * 8 + cb]);
        qf[ks][2] = __float_as_uint(Pt[(wrow + r) * PAD + ks * 8 + cb + 4]);
        qf[ks][3] = __float_as_uint(Pt[(wrow + 8 + r) * PAD + ks * 8 + cb + 4]);
    }
    __syncthreads();

    float of[8][4];
#pragma unroll
    for (int dt = 0; dt < 8; dt++)
#pragma unroll
        for (int i = 0; i < 4; i++) of[dt][i] = 0.f;
    float m0r = -1e30f, m1r = -1e30f, l0 = 0.f, l1 = 0.f;

    const int nkt = qt * 2 + 2;

    for (int kt = 0; kt < nkt; kt++) {
        const int k0 = kt * 64;
        __syncthreads();

#pragma unroll
        for (int i = 0; i < 4; i++) {
            int idx = tid + i * 256;
            int kk = idx >> 4, ch = idx & 15;
            float4 v = *(const float4*)&Kb[(size_t)(k0 + kk) * KVD + ch * 4];
            *(float4*)&Ks[kk * PAD + ((ch * 4) ^ ((kk & 3) << 3))] = v;
        }
#pragma unroll
        for (int i = 0; i < 4; i++) {
            int kk = (tid & 15) + 16 * i;
            int d0 = (tid >> 4) * 4;
            float4 v = *(const float4*)&Vb[(size_t)(k0 + kk) * KVD + d0];
            Vt[(d0 + 0) * PAD + (kk ^ 0)]  = v.x;
            Vt[(d0 + 1) * PAD + (kk ^ 8)]  = v.y;
            Vt[(d0 + 2) * PAD + (kk ^ 16)] = v.z;
            Vt[(d0 + 3) * PAD + (kk ^ 24)] = v.w;
        }
        __syncthreads();

        const bool active = (k0 <= q0 + wrow + 15);
        if (active) {
            float sf[8][4];
#pragma unroll
            for (int nt = 0; nt < 8; nt++)
#pragma unroll
                for (int i = 0; i < 4; i++) sf[nt][i] = 0.f;
#pragma unroll
            for (int ks = 0; ks < 8; ks++) {
                const int c = ((ks * 8 + cb) ^ sw);
#pragma unroll
                for (int nt = 0; nt < 8; nt++) {
                    const float* kp = &Ks[(nt * 8 + r) * PAD + c];
                    uint32_t bb[2] = { __float_as_uint(kp[0]), __float_as_uint(kp[4]) };
                    mma_tf32(sf[nt], qf[ks], bb);
                }
            }
            if (k0 + 63 > q0 + wrow) {
                const int qr0 = q0 + wrow + r;
                const int qr1 = qr0 + 8;
#pragma unroll
                for (int nt = 0; nt < 8; nt++) {
                    const int kvc = k0 + nt * 8 + cb * 2;
                    if (kvc > qr0)     sf[nt][0] = -1e30f;
                    if (kvc + 1 > qr0) sf[nt][1] = -1e30f;
                    if (kvc > qr1)     sf[nt][2] = -1e30f;
                    if (kvc + 1 > qr1) sf[nt][3] = -1e30f;
                }
            }
            float mx0 = m0r, mx1 = m1r;
#pragma unroll
            for (int nt = 0; nt < 8; nt++) {
                mx0 = fmaxf(mx0, fmaxf(sf[nt][0], sf[nt][1]));
                mx1 = fmaxf(mx1, fmaxf(sf[nt][2], sf[nt][3]));
            }
            mx0 = fmaxf(mx0, __shfl_xor_sync(0xffffffffu, mx0, 1));
            mx0 = fmaxf(mx0, __shfl_xor_sync(0xffffffffu, mx0, 2));
            mx1 = fmaxf(mx1, __shfl_xor_sync(0xffffffffu, mx1, 1));
            mx1 = fmaxf(mx1, __shfl_xor_sync(0xffffffffu, mx1, 2));
            const float a0 = __expf(m0r - mx0), a1 = __expf(m1r - mx1);
            m0r = mx0; m1r = mx1;
            float s0 = 0.f, s1 = 0.f;
#pragma unroll
            for (int nt = 0; nt < 8; nt++) {
                float p00 = __expf(sf[nt][0] - mx0);
                float p01 = __expf(sf[nt][1] - mx0);
                float p10 = __expf(sf[nt][2] - mx1);
                float p11 = __expf(sf[nt][3] - mx1);
                s0 += p00 + p01; s1 += p10 + p11;
                *(float2*)&Pt[(wrow + r) * PAD + nt * 8 + cb * 2] =
                    make_float2(f2tf32f(p00), f2tf32f(p01));
                *(float2*)&Pt[(wrow + 8 + r) * PAD + nt * 8 + cb * 2] =
                    make_float2(f2tf32f(p10), f2tf32f(p11));
            }
            s0 += __shfl_xor_sync(0xffffffffu, s0, 1);
            s0 += __shfl_xor_sync(0xffffffffu, s0, 2);
            s1 += __shfl_xor_sync(0xffffffffu, s1, 1);
            s1 += __shfl_xor_sync(0xffffffffu, s1, 2);
            l0 = l0 * a0 + s0;
            l1 = l1 * a1 + s1;
#pragma unroll
            for (int dt = 0; dt < 8; dt++) {
                of[dt][0] *= a0; of[dt][1] *= a0;
                of[dt][2] *= a1; of[dt][3] *= a1;
            }
            __syncwarp();
#pragma unroll
            for (int ks = 0; ks < 8; ks++) {
                uint32_t a[4];
                a[0] = __float_as_uint(Pt[(wrow + r) * PAD + ks * 8 + cb]);
                a[1] = __float_as_uint(Pt[(wrow + 8 + r) * PAD + ks * 8 + cb]);
                a[2] = __float_as_uint(Pt[(wrow + r) * PAD + ks * 8 + cb + 4]);
                a[3] = __float_as_uint(Pt[(wrow + 8 + r) * PAD + ks * 8 + cb + 4]);
                const int c = ((ks * 8 + cb) ^ sw);
#pragma unroll
                for (int dt = 0; dt < 8; dt++) {
                    const float* vp = &Vt[(dt * 8 + r) * PAD + c];
                    uint32_t bb[2] = { __float_as_uint(vp[0]), __float_as_uint(vp[4]) };
                    mma_tf32(of[dt], a, bb);
                }
            }
        }
    }

    // epilogue: write ctx tf32-rounded (final GEMM reads it raw)
    const float i0 = 1.f / l0, i1 = 1.f / l1;
    float* C0 = g_C + ((size_t)b * SQ + q0 + wrow + r) * DM + h * HDIM;
    float* C1 = C0 + 8 * DM;
#pragma unroll
    for (int dt = 0; dt < 8; dt++) {
        const int col = dt * 8 + cb * 2;
        *(float2*)&C0[col] = make_float2(f2tf32f(of[dt][0] * i0), f2tf32f(of[dt][1] * i0));
        *(float2*)&C1[col] = make_float2(f2tf32f(of[dt][2] * i1), f2tf32f(of[dt][3] * i1));
    }
}

// ---------------------------------------------------------------------------
extern "C" void kernel_launch(void* const* d_in, const int* in_sizes, int n_in,
                              void* d_out, int out_size)
{
    (void)in_sizes; (void)n_in; (void)out_size;
    const float* x  = (const float*)d_in[0];
    const float* Wq = (const float*)d_in[1];
    const float* Wk = (const float*)d_in[2];
    const float* Wv = (const float*)d_in[3];
    const float* Wo = (const float*)d_in[4];
    float* out = (float*)d_out;

    const int M = BATCH * SQ;   // 4096

    cudaFuncSetAttribute(gemm_tc32, cudaFuncAttributeMaxDynamicSharedMemorySize, GEMM_SMEM);
    cudaFuncSetAttribute(gqa_attn_tc, cudaFuncAttributeMaxDynamicSharedMemorySize, ATTN_SMEM);

    float* xt; cudaGetSymbolAddress((void**)&xt, g_Xt);
    float* wt; cudaGetSymbolAddress((void**)&wt, g_Wt);

    // Pre-convert x and weights to tf32 bit patterns (rna, once)
    {
        int n4 = (int)((size_t)M * DM / 4);
        cvt_tf32_k<<<(n4 + 255) / 256, 256>>>((const float4*)x, (float4*)xt, n4);
        n4 = DM * DM / 4;
        cvt_tf32_k<<<(n4 + 255) / 256, 256>>>((const float4*)Wq, (float4*)(wt + WQ_OFF), n4);
        n4 = KVD * DM / 4;
        cvt_tf32_k<<<(n4 + 255) / 256, 256>>>((const float4*)Wk, (float4*)(wt + WK_OFF), n4);
        cvt_tf32_k<<<(n4 + 255) / 256, 256>>>((const float4*)Wv, (float4*)(wt + WV_OFF), n4);
        n4 = DM * DM / 4;
        cvt_tf32_k<<<(n4 + 255) / 256, 256>>>((const float4*)Wo, (float4*)(wt + WO_OFF), n4);
    }

    // Q = x @ Wq^T
    gemm_tc32<<<dim3(DM / 128, M / 128), 128, GEMM_SMEM>>>(0, WQ_OFF, 0, nullptr, M, DM, DM);
    // K = x @ Wk^T
    gemm_tc32<<<dim3(KVD / 128, M / 128), 128, GEMM_SMEM>>>(0, WK_OFF, 1, nullptr, M, KVD, DM);
    // V = x @ Wv^T
    gemm_tc32<<<dim3(KVD / 128, M / 128), 128, GEMM_SMEM>>>(0, WV_OFF, 2, nullptr, M, KVD, DM);
    // Causal GQA attention -> g_C
    gqa_attn_tc<<<dim3(SQ / 128, BATCH * NH), 256, ATTN_SMEM>>>();
    // out = ctx @ Wo^T
    gemm_tc32<<<dim3(DM / 128, M / 128), 128, GEMM_SMEM>>>(1, WO_OFF, 3, out, M, DM, DM);
}

// round 7
// speedup vs baseline: 1.0971x; 1.0971x over previous
#include <cuda_runtime.h>
#include <math.h>
#include <stdint.h>

// Problem constants
#define BATCH 2
#define SQ    2048
#define DM    2048     // model dim
#define KVD   512      // G*HD
#define NH    32       // heads
#define HDIM  64       // head dim

// Scratch (allocation-free rule: __device__ globals)
__device__ float g_Q[(size_t)BATCH * SQ * DM];   // tf32-rounded
__device__ float g_K[(size_t)BATCH * SQ * KVD];  // tf32-rounded
__device__ float g_V[(size_t)BATCH * SQ * KVD];  // tf32-rounded
__device__ float g_C[(size_t)BATCH * SQ * DM];   // ctx, tf32-rounded
__device__ float g_Xt[(size_t)BATCH * SQ * DM];  // x, tf32-rounded
// packed tf32 weights: Wq | Wk | Wv | Wo
#define WQ_OFF 0
#define WK_OFF (2048 * 2048)
#define WV_OFF (WK_OFF + 512 * 2048)
#define WO_OFF (WV_OFF + 512 * 2048)
__device__ float g_Wt[WO_OFF + 2048 * 2048];

// ---------------------------------------------------------------------------
// helpers
// ---------------------------------------------------------------------------
__device__ __forceinline__ uint32_t smem_u32(const void* p) {
    uint32_t a;
    asm("{ .reg .u64 t; cvta.to.shared.u64 t, %1; cvt.u32.u64 %0, t; }"
        : "=r"(a) : "l"(p));
    return a;
}
__device__ __forceinline__ void cp_async16(uint32_t dst, const void* src) {
    asm volatile("cp.async.cg.shared.global [%0], [%1], 16;" :: "r"(dst), "l"(src));
}
__device__ __forceinline__ void cp_commit() {
    asm volatile("cp.async.commit_group;" ::: "memory");
}
template <int N>
__device__ __forceinline__ void cp_wait() {
    asm volatile("cp.async.wait_group %0;" :: "n"(N) : "memory");
}
__device__ __forceinline__ uint32_t f2tf32(float f) {
    uint32_t r;
    asm("cvt.rna.tf32.f32 %0, %1;" : "=r"(r) : "f"(f));
    return r;
}
__device__ __forceinline__ float f2tf32f(float f) {
    return __uint_as_float(f2tf32(f));
}
__device__ __forceinline__ void mma_tf32(float* c, const uint32_t* a, const uint32_t* b) {
    asm volatile(
        "mma.sync.aligned.m16n8k8.row.col.f32.tf32.tf32.f32 "
        "{%0,%1,%2,%3}, {%4,%5,%6,%7}, {%8,%9}, {%0,%1,%2,%3};"
        : "+f"(c[0]), "+f"(c[1]), "+f"(c[2]), "+f"(c[3])
        : "r"(a[0]), "r"(a[1]), "r"(a[2]), "r"(a[3]), "r"(b[0]), "r"(b[1]));
}
__device__ __forceinline__ void ldsm_x4(uint32_t* r, uint32_t addr) {
    asm volatile("ldmatrix.sync.aligned.m8n8.x4.shared.b16 {%0,%1,%2,%3}, [%4];"
                 : "=r"(r[0]), "=r"(r[1]), "=r"(r[2]), "=r"(r[3]) : "r"(addr));
}

// ---------------------------------------------------------------------------
// One-shot fp32 -> tf32-bits conversion (bandwidth kernel)
// ---------------------------------------------------------------------------
__global__ __launch_bounds__(256) void cvt_tf32_k(const float4* __restrict__ src,
                                                  float4* __restrict__ dst, int n4)
{
    int i = blockIdx.x * 256 + threadIdx.x;
    if (i < n4) {
        float4 v = src[i];
        dst[i] = make_float4(f2tf32f(v.x), f2tf32f(v.y), f2tf32f(v.z), f2tf32f(v.w));
    }
}

// ---------------------------------------------------------------------------
// TF32 mma.sync GEMM on pre-converted data:  C[M,N] = A[M,K] . W[N,K]^T
// CTA: 128x128 tile, BK=32, 256 threads (8 warps, 2m x 4n; warp tile 64x32).
// cp.async double-buffered smem; fragment loads via ldmatrix (tf32-as-b16x2).
// ---------------------------------------------------------------------------
#define ASTRIDE 36
#define STG_FLT (2 * 128 * ASTRIDE)         // floats per stage (A + B) = 9216
#define GEMM_SMEM (2 * STG_FLT * 4)         // 73728 bytes

__global__ __launch_bounds__(256, 2) void gemm_tc32(
    int asel, int woff, int csel, float* __restrict__ Cext,
    int M, int N, int K)
{
    extern __shared__ float sm[];
    const uint32_t sb = smem_u32(sm);
    const float* A = asel ? g_C : g_Xt;
    const float* W = g_Wt + woff;
    float* C = (csel == 0) ? g_Q : (csel == 1) ? g_K : (csel == 2) ? g_V : Cext;

    const int tid = threadIdx.x;
    const int wid = tid >> 5;
    const int lane = tid & 31;
    const int m0 = blockIdx.y * 128;
    const int n0 = blockIdx.x * 128;
    const int wm0 = (wid >> 2) * 64;
    const int wn0 = (wid & 3) * 32;

    // ldmatrix lane roles (t = lane/8, lt = lane%8)
    const int lt = lane & 7;
    const int tt = lane >> 3;
    // A tiles: t0 (r,c) t1 (r+8,c) t2 (r,c+4) t3 (r+8,c+4)
    const int arow = wm0 + lt + (tt & 1) * 8;
    const int acol = (tt >> 1) * 4;
    // B tiles: t0 (n,k) t1 (n,k+4) t2 (n+8,k) t3 (n+8,k+4)
    const int brow = wn0 + lt + (tt >> 1) * 8;
    const int bcol = (tt & 1) * 4;

    float c[4][4][4];
#pragma unroll
    for (int mt = 0; mt < 4; mt++)
#pragma unroll
        for (int nt = 0; nt < 4; nt++)
#pragma unroll
            for (int i = 0; i < 4; i++) c[mt][nt][i] = 0.f;

    const int nk = K / 32;

    auto issue = [&](int kt) {
        const int buf = kt & 1;
        const uint32_t abase = sb + buf * STG_FLT * 4;
        const uint32_t bbase = abase + 128 * ASTRIDE * 4;
        const int k0 = kt * 32;
#pragma unroll
        for (int i = 0; i < 4; i++) {
            int idx = tid + i * 256;
            int row = idx >> 3;
            int ch = idx & 7;
            cp_async16(abase + (row * ASTRIDE + ch * 4) * 4,
                       &A[(size_t)(m0 + row) * K + k0 + ch * 4]);
            cp_async16(bbase + (row * ASTRIDE + ch * 4) * 4,
                       &W[(size_t)(n0 + row) * K + k0 + ch * 4]);
        }
        cp_commit();
    };

    issue(0);

    for (int kt = 0; kt < nk; kt++) {
        if (kt + 1 < nk) {
            issue(kt + 1);
            cp_wait<1>();
        } else {
            cp_wait<0>();
        }
        __syncthreads();

        const uint32_t stg = sb + (kt & 1) * STG_FLT * 4;
        const uint32_t a_base = stg + (arow * ASTRIDE + acol) * 4;
        const uint32_t b_base = stg + 128 * ASTRIDE * 4 + (brow * ASTRIDE + bcol) * 4;

#pragma unroll
        for (int ks = 0; ks < 4; ks++) {
            uint32_t a[4][4], b[2][4];
#pragma unroll
            for (int mt = 0; mt < 4; mt++)
                ldsm_x4(a[mt], a_base + (mt * 16 * ASTRIDE + ks * 8) * 4);
#pragma unroll
            for (int np = 0; np < 2; np++)
                ldsm_x4(b[np], b_base + (np * 16 * ASTRIDE + ks * 8) * 4);
#pragma unroll
            for (int mt = 0; mt < 4; mt++)
#pragma unroll
                for (int nt = 0; nt < 4; nt++)
                    mma_tf32(c[mt][nt], a[mt], &b[nt >> 1][(nt & 1) * 2]);
        }
        __syncthreads();
    }

    const bool rnd = (csel != 3);
#pragma unroll
    for (int mt = 0; mt < 4; mt++) {
        const int r0 = m0 + wm0 + mt * 16 + (lane >> 2);
#pragma unroll
        for (int nt = 0; nt < 4; nt++) {
            const int col = n0 + wn0 + nt * 8 + (lane & 3) * 2;
            float v0 = c[mt][nt][0], v1 = c[mt][nt][1];
            float v2 = c[mt][nt][2], v3 = c[mt][nt][3];
            if (rnd) {
                v0 = f2tf32f(v0); v1 = f2tf32f(v1);
                v2 = f2tf32f(v2); v3 = f2tf32f(v3);
            }
            *(float2*)&C[(size_t)r0 * N + col] = make_float2(v0, v1);
            *(float2*)&C[(size_t)(r0 + 8) * N + col] = make_float2(v2, v3);
        }
    }
}

// ---------------------------------------------------------------------------
// Tensor-core causal GQA flash attention (tf32 mma, fp32 softmax).
// CTA: (qt, b*32+h); 256 threads = 8 warps; BQ=128 (16 q-rows/warp), BKV=64.
// Q/K/V arrive pre-rounded to tf32 (GEMM epilogue) -> loads are pure copies.
// ---------------------------------------------------------------------------
#define PAD 68
#define ATTN_SMEM ((64 * PAD + 64 * PAD + 128 * PAD) * 4)   // 69632 B

__global__ __launch_bounds__(256, 2) void gqa_attn_tc()
{
    extern __shared__ float asm_[];
    float* Ks = asm_;                 // [64][PAD]
    float* Vt = Ks + 64 * PAD;        // [64][PAD]
    float* Pt = Vt + 64 * PAD;        // [128][PAD]

    const int tid = threadIdx.x;
    const int w = tid >> 5;
    const int lane = tid & 31;
    const int r = lane >> 2;
    const int cb = lane & 3;
    const int qt = blockIdx.x;
    const int bh = blockIdx.y;
    const int b = bh >> 5, h = bh & 31, g = h >> 2;
    const int q0 = qt * 128;
    const int wrow = w * 16;
    const int sw = (r & 3) << 3;

    const float* Qb = g_Q + (size_t)b * SQ * DM + h * HDIM;
    const float* Kb = g_K + (size_t)b * SQ * KVD + g * HDIM;
    const float* Vb = g_V + (size_t)b * SQ * KVD + g * HDIM;

    // Stage Q (x 0.125 exact; inputs already tf32-rounded) into Pt
#pragma unroll
    for (int i = 0; i < 8; i++) {
        int idx = tid + i * 256;
        int row = idx >> 4, ch = idx & 15;
        float4 v = *(const float4*)&Qb[(size_t)(q0 + row) * DM + ch * 4];
        float* dst = &Pt[row * PAD + ch * 4];
        dst[0] = v.x * 0.125f;
        dst[1] = v.y * 0.125f;
        dst[2] = v.z * 0.125f;
        dst[3] = v.w * 0.125f;
    }
    __syncthreads();

    uint32_t qf[8][4];
#pragma unroll
    for (int ks = 0; ks < 8; ks++) {
        qf[ks][0] = __float_as_uint(Pt[(wrow + r) * PAD + ks * 8 + cb]);
        qf[ks][1] = __float_as_uint(Pt[(wrow + 8 + r) * PAD + ks * 8 + cb]);
        qf[ks][2] = __float_as_uint(Pt[(wrow + r) * PAD + ks * 8 + cb + 4]);
        qf[ks][3] = __float_as_uint(Pt[(wrow + 8 + r) * PAD + ks * 8 + cb + 4]);
    }
    __syncthreads();

    float of[8][4];
#pragma unroll
    for (int dt = 0; dt < 8; dt++)
#pragma unroll
        for (int i = 0; i < 4; i++) of[dt][i] = 0.f;
    float m0r = -1e30f, m1r = -1e30f, l0 = 0.f, l1 = 0.f;

    const int nkt = qt * 2 + 2;

    for (int kt = 0; kt < nkt; kt++) {
        const int k0 = kt * 64;
        __syncthreads();

#pragma unroll
        for (int i = 0; i < 4; i++) {
            int idx = tid + i * 256;
            int kk = idx >> 4, ch = idx & 15;
            float4 v = *(const float4*)&Kb[(size_t)(k0 + kk) * KVD + ch * 4];
            *(float4*)&Ks[kk * PAD + ((ch * 4) ^ ((kk & 3) << 3))] = v;
        }
#pragma unroll
        for (int i = 0; i < 4; i++) {
            int kk = (tid & 15) + 16 * i;
            int d0 = (tid >> 4) * 4;
            float4 v = *(const float4*)&Vb[(size_t)(k0 + kk) * KVD + d0];
            Vt[(d0 + 0) * PAD + (kk ^ 0)]  = v.x;
            Vt[(d0 + 1) * PAD + (kk ^ 8)]  = v.y;
            Vt[(d0 + 2) * PAD + (kk ^ 16)] = v.z;
            Vt[(d0 + 3) * PAD + (kk ^ 24)] = v.w;
        }
        __syncthreads();

        const bool active = (k0 <= q0 + wrow + 15);
        if (active) {
            float sf[8][4];
#pragma unroll
            for (int nt = 0; nt < 8; nt++)
#pragma unroll
                for (int i = 0; i < 4; i++) sf[nt][i] = 0.f;
#pragma unroll
            for (int ks = 0; ks < 8; ks++) {
                const int c = ((ks * 8 + cb) ^ sw);
#pragma unroll
                for (int nt = 0; nt < 8; nt++) {
                    const float* kp = &Ks[(nt * 8 + r) * PAD + c];
                    uint32_t bb[2] = { __float_as_uint(kp[0]), __float_as_uint(kp[4]) };
                    mma_tf32(sf[nt], qf[ks], bb);
                }
            }
            if (k0 + 63 > q0 + wrow) {
                const int qr0 = q0 + wrow + r;
                const int qr1 = qr0 + 8;
#pragma unroll
                for (int nt = 0; nt < 8; nt++) {
                    const int kvc = k0 + nt * 8 + cb * 2;
                    if (kvc > qr0)     sf[nt][0] = -1e30f;
                    if (kvc + 1 > qr0) sf[nt][1] = -1e30f;
                    if (kvc > qr1)     sf[nt][2] = -1e30f;
                    if (kvc + 1 > qr1) sf[nt][3] = -1e30f;
                }
            }
            float mx0 = m0r, mx1 = m1r;
#pragma unroll
            for (int nt = 0; nt < 8; nt++) {
                mx0 = fmaxf(mx0, fmaxf(sf[nt][0], sf[nt][1]));
                mx1 = fmaxf(mx1, fmaxf(sf[nt][2], sf[nt][3]));
            }
            mx0 = fmaxf(mx0, __shfl_xor_sync(0xffffffffu, mx0, 1));
            mx0 = fmaxf(mx0, __shfl_xor_sync(0xffffffffu, mx0, 2));
            mx1 = fmaxf(mx1, __shfl_xor_sync(0xffffffffu, mx1, 1));
            mx1 = fmaxf(mx1, __shfl_xor_sync(0xffffffffu, mx1, 2));
            const float a0 = __expf(m0r - mx0), a1 = __expf(m1r - mx1);
            m0r = mx0; m1r = mx1;
            float s0 = 0.f, s1 = 0.f;
#pragma unroll
            for (int nt = 0; nt < 8; nt++) {
                float p00 = __expf(sf[nt][0] - mx0);
                float p01 = __expf(sf[nt][1] - mx0);
                float p10 = __expf(sf[nt][2] - mx1);
                float p11 = __expf(sf[nt][3] - mx1);
                s0 += p00 + p01; s1 += p10 + p11;
                *(float2*)&Pt[(wrow + r) * PAD + nt * 8 + cb * 2] =
                    make_float2(f2tf32f(p00), f2tf32f(p01));
                *(float2*)&Pt[(wrow + 8 + r) * PAD + nt * 8 + cb * 2] =
                    make_float2(f2tf32f(p10), f2tf32f(p11));
            }
            s0 += __shfl_xor_sync(0xffffffffu, s0, 1);
            s0 += __shfl_xor_sync(0xffffffffu, s0, 2);
            s1 += __shfl_xor_sync(0xffffffffu, s1, 1);
            s1 += __shfl_xor_sync(0xffffffffu, s1, 2);
            l0 = l0 * a0 + s0;
            l1 = l1 * a1 + s1;
#pragma unroll
            for (int dt = 0; dt < 8; dt++) {
                of[dt][0] *= a0; of[dt][1] *= a0;
                of[dt][2] *= a1; of[dt][3] *= a1;
            }
            __syncwarp();
#pragma unroll
            for (int ks = 0; ks < 8; ks++) {
                uint32_t a[4];
                a[0] = __float_as_uint(Pt[(wrow + r) * PAD + ks * 8 + cb]);
                a[1] = __float_as_uint(Pt[(wrow + 8 + r) * PAD + ks * 8 + cb]);
                a[2] = __float_as_uint(Pt[(wrow + r) * PAD + ks * 8 + cb + 4]);
                a[3] = __float_as_uint(Pt[(wrow + 8 + r) * PAD + ks * 8 + cb + 4]);
                const int c = ((ks * 8 + cb) ^ sw);
#pragma unroll
                for (int dt = 0; dt < 8; dt++) {
                    const float* vp = &Vt[(dt * 8 + r) * PAD + c];
                    uint32_t bb[2] = { __float_as_uint(vp[0]), __float_as_uint(vp[4]) };
                    mma_tf32(of[dt], a, bb);
                }
            }
        }
    }

    // epilogue: write ctx tf32-rounded (final GEMM reads it raw)
    const float i0 = 1.f / l0, i1 = 1.f / l1;
    float* C0 = g_C + ((size_t)b * SQ + q0 + wrow + r) * DM + h * HDIM;
    float* C1 = C0 + 8 * DM;
#pragma unroll
    for (int dt = 0; dt < 8; dt++) {
        const int col = dt * 8 + cb * 2;
        *(float2*)&C0[col] = make_float2(f2tf32f(of[dt][0] * i0), f2tf32f(of[dt][1] * i0));
        *(float2*)&C1[col] = make_float2(f2tf32f(of[dt][2] * i1), f2tf32f(of[dt][3] * i1));
    }
}

// ---------------------------------------------------------------------------
extern "C" void kernel_launch(void* const* d_in, const int* in_sizes, int n_in,
                              void* d_out, int out_size)
{
    (void)in_sizes; (void)n_in; (void)out_size;
    const float* x  = (const float*)d_in[0];
    const float* Wq = (const float*)d_in[1];
    const float* Wk = (const float*)d_in[2];
    const float* Wv = (const float*)d_in[3];
    const float* Wo = (const float*)d_in[4];
    float* out = (float*)d_out;

    const int M = BATCH * SQ;   // 4096

    cudaFuncSetAttribute(gemm_tc32, cudaFuncAttributeMaxDynamicSharedMemorySize, GEMM_SMEM);
    cudaFuncSetAttribute(gqa_attn_tc, cudaFuncAttributeMaxDynamicSharedMemorySize, ATTN_SMEM);

    float* xt; cudaGetSymbolAddress((void**)&xt, g_Xt);
    float* wt; cudaGetSymbolAddress((void**)&wt, g_Wt);

    // Pre-convert x and weights to tf32 bit patterns (rna, once)
    {
        int n4 = (int)((size_t)M * DM / 4);
        cvt_tf32_k<<<(n4 + 255) / 256, 256>>>((const float4*)x, (float4*)xt, n4);
        n4 = DM * DM / 4;
        cvt_tf32_k<<<(n4 + 255) / 256, 256>>>((const float4*)Wq, (float4*)(wt + WQ_OFF), n4);
        n4 = KVD * DM / 4;
        cvt_tf32_k<<<(n4 + 255) / 256, 256>>>((const float4*)Wk, (float4*)(wt + WK_OFF), n4);
        cvt_tf32_k<<<(n4 + 255) / 256, 256>>>((const float4*)Wv, (float4*)(wt + WV_OFF), n4);
        n4 = DM * DM / 4;
        cvt_tf32_k<<<(n4 + 255) / 256, 256>>>((const float4*)Wo, (float4*)(wt + WO_OFF), n4);
    }

    // Q = x @ Wq^T
    gemm_tc32<<<dim3(DM / 128, M / 128), 256, GEMM_SMEM>>>(0, WQ_OFF, 0, nullptr, M, DM, DM);
    // K = x @ Wk^T
    gemm_tc32<<<dim3(KVD / 128, M / 128), 256, GEMM_SMEM>>>(0, WK_OFF, 1, nullptr, M, KVD, DM);
    // V = x @ Wv^T
    gemm_tc32<<<dim3(KVD / 128, M / 128), 256, GEMM_SMEM>>>(0, WV_OFF, 2, nullptr, M, KVD, DM);
    // Causal GQA attention -> g_C
    gqa_attn_tc<<<dim3(SQ / 128, BATCH * NH), 256, ATTN_SMEM>>>();
    // out = ctx @ Wo^T
    gemm_tc32<<<dim3(DM / 128, M / 128), 256, GEMM_SMEM>>>(1, WO_OFF, 3, out, M, DM, DM);
}

// round 8
// speedup vs baseline: 1.2385x; 1.1289x over previous
#include <cuda_runtime.h>
#include <math.h>
#include <stdint.h>

// Problem constants
#define BATCH 2
#define SQ    2048
#define DM    2048     // model dim
#define KVD   512      // G*HD
#define NH    32       // heads
#define HDIM  64       // head dim

// Scratch (allocation-free rule: __device__ globals)
__device__ float g_Q[(size_t)BATCH * SQ * DM];   // tf32-rounded
__device__ float g_K[(size_t)BATCH * SQ * KVD];  // tf32-rounded
__device__ float g_V[(size_t)BATCH * SQ * KVD];  // tf32-rounded
__device__ float g_C[(size_t)BATCH * SQ * DM];   // ctx, tf32-rounded
__device__ float g_Xt[(size_t)BATCH * SQ * DM];  // x, tf32-rounded
// packed tf32 weights: Wq | Wk | Wv | Wo  (QKV contiguous -> fused GEMM)
#define WQ_OFF 0
#define WK_OFF (2048 * 2048)
#define WV_OFF (WK_OFF + 512 * 2048)
#define WO_OFF (WV_OFF + 512 * 2048)
__device__ float g_Wt[WO_OFF + 2048 * 2048];

// ---------------------------------------------------------------------------
// helpers
// ---------------------------------------------------------------------------
__device__ __forceinline__ uint32_t smem_u32(const void* p) {
    uint32_t a;
    asm("{ .reg .u64 t; cvta.to.shared.u64 t, %1; cvt.u32.u64 %0, t; }"
        : "=r"(a) : "l"(p));
    return a;
}
__device__ __forceinline__ void cp_async16(uint32_t dst, const void* src) {
    asm volatile("cp.async.cg.shared.global [%0], [%1], 16;" :: "r"(dst), "l"(src));
}
__device__ __forceinline__ void cp_commit() {
    asm volatile("cp.async.commit_group;" ::: "memory");
}
template <int N>
__device__ __forceinline__ void cp_wait() {
    asm volatile("cp.async.wait_group %0;" :: "n"(N) : "memory");
}
__device__ __forceinline__ uint32_t f2tf32(float f) {
    uint32_t r;
    asm("cvt.rna.tf32.f32 %0, %1;" : "=r"(r) : "f"(f));
    return r;
}
__device__ __forceinline__ float f2tf32f(float f) {
    return __uint_as_float(f2tf32(f));
}
__device__ __forceinline__ void mma_tf32(float* c, const uint32_t* a, const uint32_t* b) {
    asm volatile(
        "mma.sync.aligned.m16n8k8.row.col.f32.tf32.tf32.f32 "
        "{%0,%1,%2,%3}, {%4,%5,%6,%7}, {%8,%9}, {%0,%1,%2,%3};"
        : "+f"(c[0]), "+f"(c[1]), "+f"(c[2]), "+f"(c[3])
        : "r"(a[0]), "r"(a[1]), "r"(a[2]), "r"(a[3]), "r"(b[0]), "r"(b[1]));
}
__device__ __forceinline__ void ldsm_x4(uint32_t* r, uint32_t addr) {
    asm volatile("ldmatrix.sync.aligned.m8n8.x4.shared.b16 {%0,%1,%2,%3}, [%4];"
                 : "=r"(r[0]), "=r"(r[1]), "=r"(r[2]), "=r"(r[3]) : "r"(addr));
}

// ---------------------------------------------------------------------------
// One-shot fp32 -> tf32-bits conversion (bandwidth kernel)
// ---------------------------------------------------------------------------
__global__ __launch_bounds__(256) void cvt_tf32_k(const float4* __restrict__ src,
                                                  float4* __restrict__ dst, int n4)
{
    int i = blockIdx.x * 256 + threadIdx.x;
    if (i < n4) {
        float4 v = src[i];
        dst[i] = make_float4(f2tf32f(v.x), f2tf32f(v.y), f2tf32f(v.z), f2tf32f(v.w));
    }
}

// ---------------------------------------------------------------------------
// TF32 mma.sync GEMM on pre-converted data:  C[M,N] = A[M,K] . W[N,K]^T
// CTA: 128x128 tile, BK=32, 256 threads (8 warps, 2m x 4n; warp tile 64x32).
// cp.async double-buffered smem; fragment loads via ldmatrix.
// csel: 0=g_Q 1=g_K 2=g_V 3=Cext 4=fused QKV (route by n0)
// ---------------------------------------------------------------------------
#define ASTRIDE 36
#define STG_FLT (2 * 128 * ASTRIDE)         // floats per stage (A + B) = 9216
#define GEMM_SMEM (2 * STG_FLT * 4)         // 73728 bytes

__global__ __launch_bounds__(256, 2) void gemm_tc32(
    int asel, int woff, int csel, float* __restrict__ Cext, int M, int K)
{
    extern __shared__ float sm[];
    const uint32_t sb = smem_u32(sm);
    const float* A = asel ? g_C : g_Xt;
    const float* W = g_Wt + woff;

    const int tid = threadIdx.x;
    const int wid = tid >> 5;
    const int lane = tid & 31;
    const int m0 = blockIdx.y * 128;
    const int n0 = blockIdx.x * 128;
    const int wm0 = (wid >> 2) * 64;
    const int wn0 = (wid & 3) * 32;

    // output routing
    float* C;
    int ldc, cbase;
    bool rnd = true;
    if (csel == 4) {
        if (n0 < 2048)      { C = g_Q; ldc = DM;  cbase = n0; }
        else if (n0 < 2560) { C = g_K; ldc = KVD; cbase = n0 - 2048; }
        else                { C = g_V; ldc = KVD; cbase = n0 - 2560; }
    } else { // csel == 3
        C = Cext; ldc = DM; cbase = n0; rnd = false;
    }

    // ldmatrix lane roles
    const int lt = lane & 7;
    const int tt = lane >> 3;
    const int arow = wm0 + lt + (tt & 1) * 8;
    const int acol = (tt >> 1) * 4;
    const int brow = wn0 + lt + (tt >> 1) * 8;
    const int bcol = (tt & 1) * 4;

    float c[4][4][4];
#pragma unroll
    for (int mt = 0; mt < 4; mt++)
#pragma unroll
        for (int nt = 0; nt < 4; nt++)
#pragma unroll
            for (int i = 0; i < 4; i++) c[mt][nt][i] = 0.f;

    const int nk = K / 32;

    auto issue = [&](int kt) {
        const int buf = kt & 1;
        const uint32_t abase = sb + buf * STG_FLT * 4;
        const uint32_t bbase = abase + 128 * ASTRIDE * 4;
        const int k0 = kt * 32;
#pragma unroll
        for (int i = 0; i < 4; i++) {
            int idx = tid + i * 256;
            int row = idx >> 3;
            int ch = idx & 7;
            cp_async16(abase + (row * ASTRIDE + ch * 4) * 4,
                       &A[(size_t)(m0 + row) * K + k0 + ch * 4]);
            cp_async16(bbase + (row * ASTRIDE + ch * 4) * 4,
                       &W[(size_t)(n0 + row) * K + k0 + ch * 4]);
        }
        cp_commit();
    };

    issue(0);

    for (int kt = 0; kt < nk; kt++) {
        if (kt + 1 < nk) {
            issue(kt + 1);
            cp_wait<1>();
        } else {
            cp_wait<0>();
        }
        __syncthreads();

        const uint32_t stg = sb + (kt & 1) * STG_FLT * 4;
        const uint32_t a_base = stg + (arow * ASTRIDE + acol) * 4;
        const uint32_t b_base = stg + 128 * ASTRIDE * 4 + (brow * ASTRIDE + bcol) * 4;

#pragma unroll
        for (int ks = 0; ks < 4; ks++) {
            uint32_t a[4][4], b[2][4];
#pragma unroll
            for (int mt = 0; mt < 4; mt++)
                ldsm_x4(a[mt], a_base + (mt * 16 * ASTRIDE + ks * 8) * 4);
#pragma unroll
            for (int np = 0; np < 2; np++)
                ldsm_x4(b[np], b_base + (np * 16 * ASTRIDE + ks * 8) * 4);
#pragma unroll
            for (int mt = 0; mt < 4; mt++)
#pragma unroll
                for (int nt = 0; nt < 4; nt++)
                    mma_tf32(c[mt][nt], a[mt], &b[nt >> 1][(nt & 1) * 2]);
        }
        __syncthreads();
    }

#pragma unroll
    for (int mt = 0; mt < 4; mt++) {
        const int r0 = m0 + wm0 + mt * 16 + (lane >> 2);
#pragma unroll
        for (int nt = 0; nt < 4; nt++) {
            const int col = cbase + wn0 + nt * 8 + (lane & 3) * 2;
            float v0 = c[mt][nt][0], v1 = c[mt][nt][1];
            float v2 = c[mt][nt][2], v3 = c[mt][nt][3];
            if (rnd) {
                v0 = f2tf32f(v0); v1 = f2tf32f(v1);
                v2 = f2tf32f(v2); v3 = f2tf32f(v3);
            }
            *(float2*)&C[(size_t)r0 * ldc + col] = make_float2(v0, v1);
            *(float2*)&C[(size_t)(r0 + 8) * ldc + col] = make_float2(v2, v3);
        }
    }
}

// ---------------------------------------------------------------------------
// Tensor-core causal GQA flash attention (tf32 mma, fp32 softmax).
// CTA: (qt, b*32+h); 256 threads = 8 warps; BQ=128 (16 q-rows/warp), BKV=64.
// cp.async double-buffered K (swizzled) + V (raw rows, stride 72 -> the PV
// B-frag scalar reads are conflict-free). Heaviest q-tiles launch first.
// ---------------------------------------------------------------------------
#define PAD   68
#define VPAD  72
#define KS_FL (64 * PAD)     // 4352 floats per K buffer
#define VR_FL (64 * VPAD)    // 4608 floats per V buffer
#define ATTN_SMEM ((2 * KS_FL + 2 * VR_FL + 128 * PAD) * 4)   // 106496 B

__global__ __launch_bounds__(256, 2) void gqa_attn_tc()
{
    extern __shared__ float asm_[];
    float* Ks = asm_;                   // 2 x [64][PAD]
    float* Vr = Ks + 2 * KS_FL;         // 2 x [64][VPAD]
    float* Pt = Vr + 2 * VR_FL;         // [128][PAD]
    const uint32_t sb = smem_u32(asm_);
    const uint32_t sbK = sb;
    const uint32_t sbV = sb + 2 * KS_FL * 4;

    const int tid = threadIdx.x;
    const int w = tid >> 5;
    const int lane = tid & 31;
    const int r = lane >> 2;
    const int cb = lane & 3;
    const int qt = (int)gridDim.x - 1 - (int)blockIdx.x;   // heavy tiles first
    const int bh = blockIdx.y;
    const int b = bh >> 5, h = bh & 31, g = h >> 2;
    const int q0 = qt * 128;
    const int wrow = w * 16;
    const int sw = (r & 3) << 3;

    const float* Qb = g_Q + (size_t)b * SQ * DM + h * HDIM;
    const float* Kb = g_K + (size_t)b * SQ * KVD + g * HDIM;
    const float* Vb = g_V + (size_t)b * SQ * KVD + g * HDIM;

    // Stage Q (x 0.125 exact; inputs already tf32-rounded) into Pt
#pragma unroll
    for (int i = 0; i < 8; i++) {
        int idx = tid + i * 256;
        int row = idx >> 4, ch = idx & 15;
        float4 v = *(const float4*)&Qb[(size_t)(q0 + row) * DM + ch * 4];
        float* dst = &Pt[row * PAD + ch * 4];
        dst[0] = v.x * 0.125f;
        dst[1] = v.y * 0.125f;
        dst[2] = v.z * 0.125f;
        dst[3] = v.w * 0.125f;
    }
    __syncthreads();

    uint32_t qf[8][4];
#pragma unroll
    for (int ks = 0; ks < 8; ks++) {
        qf[ks][0] = __float_as_uint(Pt[(wrow + r) * PAD + ks * 8 + cb]);
        qf[ks][1] = __float_as_uint(Pt[(wrow + 8 + r) * PAD + ks * 8 + cb]);
        qf[ks][2] = __float_as_uint(Pt[(wrow + r) * PAD + ks * 8 + cb + 4]);
        qf[ks][3] = __float_as_uint(Pt[(wrow + 8 + r) * PAD + ks * 8 + cb + 4]);
    }
    __syncthreads();

    float of[8][4];
#pragma unroll
    for (int dt = 0; dt < 8; dt++)
#pragma unroll
        for (int i = 0; i < 4; i++) of[dt][i] = 0.f;
    float m0r = -1e30f, m1r = -1e30f, l0 = 0.f, l1 = 0.f;

    const int nkt = qt * 2 + 2;

    auto issue_tile = [&](int kt) {
        const int buf = kt & 1;
        const uint32_t kbuf = sbK + buf * KS_FL * 4;
        const uint32_t vbuf = sbV + buf * VR_FL * 4;
        const int k0 = kt * 64;
#pragma unroll
        for (int i = 0; i < 4; i++) {
            int idx = tid + i * 256;
            int kk = idx >> 4, ch = idx & 15;
            const float* src = &Kb[(size_t)(k0 + kk) * KVD + ch * 4];
            cp_async16(kbuf + (kk * PAD + ((ch * 4) ^ ((kk & 3) << 3))) * 4, src);
            cp_async16(vbuf + (kk * VPAD + ch * 4) * 4,
                       &Vb[(size_t)(k0 + kk) * KVD + ch * 4]);
        }
        cp_commit();
    };

    issue_tile(0);

    for (int kt = 0; kt < nkt; kt++) {
        if (kt + 1 < nkt) {
            issue_tile(kt + 1);
            cp_wait<1>();
        } else {
            cp_wait<0>();
        }
        __syncthreads();

        const float* KsT = Ks + (kt & 1) * KS_FL;
        const float* VrT = Vr + (kt & 1) * VR_FL;
        const int k0 = kt * 64;

        const bool active = (k0 <= q0 + wrow + 15);
        if (active) {
            float sf[8][4];
#pragma unroll
            for (int nt = 0; nt < 8; nt++)
#pragma unroll
                for (int i = 0; i < 4; i++) sf[nt][i] = 0.f;
#pragma unroll
            for (int ks = 0; ks < 8; ks++) {
                const int c = ((ks * 8 + cb) ^ sw);
#pragma unroll
                for (int nt = 0; nt < 8; nt++) {
                    const float* kp = &KsT[(nt * 8 + r) * PAD + c];
                    uint32_t bb[2] = { __float_as_uint(kp[0]), __float_as_uint(kp[4]) };
                    mma_tf32(sf[nt], qf[ks], bb);
                }
            }
            if (k0 + 63 > q0 + wrow) {
                const int qr0 = q0 + wrow + r;
                const int qr1 = qr0 + 8;
#pragma unroll
                for (int nt = 0; nt < 8; nt++) {
                    const int kvc = k0 + nt * 8 + cb * 2;
                    if (kvc > qr0)     sf[nt][0] = -1e30f;
                    if (kvc + 1 > qr0) sf[nt][1] = -1e30f;
                    if (kvc > qr1)     sf[nt][2] = -1e30f;
                    if (kvc + 1 > qr1) sf[nt][3] = -1e30f;
                }
            }
            float mx0 = m0r, mx1 = m1r;
#pragma unroll
            for (int nt = 0; nt < 8; nt++) {
                mx0 = fmaxf(mx0, fmaxf(sf[nt][0], sf[nt][1]));
                mx1 = fmaxf(mx1, fmaxf(sf[nt][2], sf[nt][3]));
            }
            mx0 = fmaxf(mx0, __shfl_xor_sync(0xffffffffu, mx0, 1));
            mx0 = fmaxf(mx0, __shfl_xor_sync(0xffffffffu, mx0, 2));
            mx1 = fmaxf(mx1, __shfl_xor_sync(0xffffffffu, mx1, 1));
            mx1 = fmaxf(mx1, __shfl_xor_sync(0xffffffffu, mx1, 2));
            const float a0 = __expf(m0r - mx0), a1 = __expf(m1r - mx1);
            m0r = mx0; m1r = mx1;
            float s0 = 0.f, s1 = 0.f;
#pragma unroll
            for (int nt = 0; nt < 8; nt++) {
                float p00 = __expf(sf[nt][0] - mx0);
                float p01 = __expf(sf[nt][1] - mx0);
                float p10 = __expf(sf[nt][2] - mx1);
                float p11 = __expf(sf[nt][3] - mx1);
                s0 += p00 + p01; s1 += p10 + p11;
                *(float2*)&Pt[(wrow + r) * PAD + nt * 8 + cb * 2] =
                    make_float2(f2tf32f(p00), f2tf32f(p01));
                *(float2*)&Pt[(wrow + 8 + r) * PAD + nt * 8 + cb * 2] =
                    make_float2(f2tf32f(p10), f2tf32f(p11));
            }
            s0 += __shfl_xor_sync(0xffffffffu, s0, 1);
            s0 += __shfl_xor_sync(0xffffffffu, s0, 2);
            s1 += __shfl_xor_sync(0xffffffffu, s1, 1);
            s1 += __shfl_xor_sync(0xffffffffu, s1, 2);
            l0 = l0 * a0 + s0;
            l1 = l1 * a1 + s1;
#pragma unroll
            for (int dt = 0; dt < 8; dt++) {
                of[dt][0] *= a0; of[dt][1] *= a0;
                of[dt][2] *= a1; of[dt][3] *= a1;
            }
            __syncwarp();
            // O += P.V  (B frags straight from raw V rows: b0=V[k][d], b1=V[k+4][d])
#pragma unroll
            for (int ks = 0; ks < 8; ks++) {
                uint32_t a[4];
                a[0] = __float_as_uint(Pt[(wrow + r) * PAD + ks * 8 + cb]);
                a[1] = __float_as_uint(Pt[(wrow + 8 + r) * PAD + ks * 8 + cb]);
                a[2] = __float_as_uint(Pt[(wrow + r) * PAD + ks * 8 + cb + 4]);
                a[3] = __float_as_uint(Pt[(wrow + 8 + r) * PAD + ks * 8 + cb + 4]);
                const float* vrow = &VrT[(ks * 8 + cb) * VPAD + r];
#pragma unroll
                for (int dt = 0; dt < 8; dt++) {
                    uint32_t bb[2] = { __float_as_uint(vrow[dt * 8]),
                                       __float_as_uint(vrow[4 * VPAD + dt * 8]) };
                    mma_tf32(of[dt], a, bb);
                }
            }
        }
        __syncthreads();
    }

    // epilogue: write ctx tf32-rounded (final GEMM reads it raw)
    const float i0 = 1.f / l0, i1 = 1.f / l1;
    float* C0 = g_C + ((size_t)b * SQ + q0 + wrow + r) * DM + h * HDIM;
    float* C1 = C0 + 8 * DM;
#pragma unroll
    for (int dt = 0; dt < 8; dt++) {
        const int col = dt * 8 + cb * 2;
        *(float2*)&C0[col] = make_float2(f2tf32f(of[dt][0] * i0), f2tf32f(of[dt][1] * i0));
        *(float2*)&C1[col] = make_float2(f2tf32f(of[dt][2] * i1), f2tf32f(of[dt][3] * i1));
    }
}

// ---------------------------------------------------------------------------
extern "C" void kernel_launch(void* const* d_in, const int* in_sizes, int n_in,
                              void* d_out, int out_size)
{
    (void)in_sizes; (void)n_in; (void)out_size;
    const float* x  = (const float*)d_in[0];
    const float* Wq = (const float*)d_in[1];
    const float* Wk = (const float*)d_in[2];
    const float* Wv = (const float*)d_in[3];
    const float* Wo = (const float*)d_in[4];
    float* out = (float*)d_out;

    const int M = BATCH * SQ;   // 4096

    cudaFuncSetAttribute(gemm_tc32, cudaFuncAttributeMaxDynamicSharedMemorySize, GEMM_SMEM);
    cudaFuncSetAttribute(gqa_attn_tc, cudaFuncAttributeMaxDynamicSharedMemorySize, ATTN_SMEM);

    float* xt; cudaGetSymbolAddress((void**)&xt, g_Xt);
    float* wt; cudaGetSymbolAddress((void**)&wt, g_Wt);

    // Pre-convert x and weights to tf32 bit patterns (rna, once)
    {
        int n4 = (int)((size_t)M * DM / 4);
        cvt_tf32_k<<<(n4 + 255) / 256, 256>>>((const float4*)x, (float4*)xt, n4);
        n4 = DM * DM / 4;
        cvt_tf32_k<<<(n4 + 255) / 256, 256>>>((const float4*)Wq, (float4*)(wt + WQ_OFF), n4);
        n4 = KVD * DM / 4;
        cvt_tf32_k<<<(n4 + 255) / 256, 256>>>((const float4*)Wk, (float4*)(wt + WK_OFF), n4);
        cvt_tf32_k<<<(n4 + 255) / 256, 256>>>((const float4*)Wv, (float4*)(wt + WV_OFF), n4);
        n4 = DM * DM / 4;
        cvt_tf32_k<<<(n4 + 255) / 256, 256>>>((const float4*)Wo, (float4*)(wt + WO_OFF), n4);
    }

    // Fused Q|K|V = x @ [Wq;Wk;Wv]^T   (3072 weight rows, contiguous)
    gemm_tc32<<<dim3(3072 / 128, M / 128), 256, GEMM_SMEM>>>(0, 0, 4, nullptr, M, DM);
    // Causal GQA attention -> g_C
    gqa_attn_tc<<<dim3(SQ / 128, BATCH * NH), 256, ATTN_SMEM>>>();
    // out = ctx @ Wo^T
    gemm_tc32<<<dim3(DM / 128, M / 128), 256, GEMM_SMEM>>>(1, WO_OFF, 3, out, M, DM);
}

// round 9
// speedup vs baseline: 1.2983x; 1.0483x over previous
#include <cuda_runtime.h>
#include <math.h>
#include <stdint.h>

// Problem constants
#define BATCH 2
#define SQ    2048
#define DM    2048     // model dim
#define KVD   512      // G*HD
#define NH    32       // heads
#define HDIM  64       // head dim

// Scratch (allocation-free rule: __device__ globals)
__device__ float g_Q[(size_t)BATCH * SQ * DM];   // tf32-rounded
__device__ float g_K[(size_t)BATCH * SQ * KVD];  // tf32-rounded
__device__ float g_V[(size_t)BATCH * SQ * KVD];  // tf32-rounded
__device__ float g_C[(size_t)BATCH * SQ * DM];   // ctx, tf32-rounded
__device__ float g_Xt[(size_t)BATCH * SQ * DM];  // x, tf32-rounded
// packed tf32 weights: Wq | Wk | Wv | Wo  (QKV contiguous -> fused GEMM)
#define WQ_OFF 0
#define WK_OFF (2048 * 2048)
#define WV_OFF (WK_OFF + 512 * 2048)
#define WO_OFF (WV_OFF + 512 * 2048)
__device__ float g_Wt[WO_OFF + 2048 * 2048];

// ---------------------------------------------------------------------------
// helpers
// ---------------------------------------------------------------------------
__device__ __forceinline__ uint32_t smem_u32(const void* p) {
    uint32_t a;
    asm("{ .reg .u64 t; cvta.to.shared.u64 t, %1; cvt.u32.u64 %0, t; }"
        : "=r"(a) : "l"(p));
    return a;
}
__device__ __forceinline__ void cp_async16(uint32_t dst, const void* src) {
    asm volatile("cp.async.cg.shared.global [%0], [%1], 16;" :: "r"(dst), "l"(src));
}
__device__ __forceinline__ void cp_commit() {
    asm volatile("cp.async.commit_group;" ::: "memory");
}
template <int N>
__device__ __forceinline__ void cp_wait() {
    asm volatile("cp.async.wait_group %0;" :: "n"(N) : "memory");
}
__device__ __forceinline__ uint32_t f2tf32(float f) {
    uint32_t r;
    asm("cvt.rna.tf32.f32 %0, %1;" : "=r"(r) : "f"(f));
    return r;
}
__device__ __forceinline__ float f2tf32f(float f) {
    return __uint_as_float(f2tf32(f));
}
__device__ __forceinline__ void mma_tf32(float* c, const uint32_t* a, const uint32_t* b) {
    asm volatile(
        "mma.sync.aligned.m16n8k8.row.col.f32.tf32.tf32.f32 "
        "{%0,%1,%2,%3}, {%4,%5,%6,%7}, {%8,%9}, {%0,%1,%2,%3};"
        : "+f"(c[0]), "+f"(c[1]), "+f"(c[2]), "+f"(c[3])
        : "r"(a[0]), "r"(a[1]), "r"(a[2]), "r"(a[3]), "r"(b[0]), "r"(b[1]));
}
__device__ __forceinline__ void ldsm_x4(uint32_t* r, uint32_t addr) {
    asm volatile("ldmatrix.sync.aligned.m8n8.x4.shared.b16 {%0,%1,%2,%3}, [%4];"
                 : "=r"(r[0]), "=r"(r[1]), "=r"(r[2]), "=r"(r[3]) : "r"(addr));
}

// ---------------------------------------------------------------------------
// One-shot fp32 -> tf32-bits conversion (bandwidth kernel)
// ---------------------------------------------------------------------------
__global__ __launch_bounds__(256) void cvt_tf32_k(const float4* __restrict__ src,
                                                  float4* __restrict__ dst, int n4)
{
    int i = blockIdx.x * 256 + threadIdx.x;
    if (i < n4) {
        float4 v = src[i];
        dst[i] = make_float4(f2tf32f(v.x), f2tf32f(v.y), f2tf32f(v.z), f2tf32f(v.w));
    }
}

// ---------------------------------------------------------------------------
// TF32 mma.sync GEMM on pre-converted data:  C[M,N] = A[M,K] . W[N,K]^T
// CTA: 128x128 tile, BK=32, 256 threads (8 warps, 2m x 4n; warp tile 64x32).
// 3-stage cp.async pipeline, ONE __syncthreads per k-tile. ldmatrix frags.
// csel: 3=Cext (raw), 4=fused QKV (route by n0, tf32-rounded)
// ---------------------------------------------------------------------------
#define ASTRIDE 36
#define STG_FLT (2 * 128 * ASTRIDE)         // floats per stage (A + B) = 9216
#define GEMM_SMEM (3 * STG_FLT * 4)         // 110592 bytes

__global__ __launch_bounds__(256, 2) void gemm_tc32(
    int asel, int woff, int csel, float* __restrict__ Cext, int M, int K)
{
    extern __shared__ float sm[];
    const uint32_t sb = smem_u32(sm);
    const float* A = asel ? g_C : g_Xt;
    const float* W = g_Wt + woff;

    const int tid = threadIdx.x;
    const int wid = tid >> 5;
    const int lane = tid & 31;
    const int m0 = blockIdx.y * 128;
    const int n0 = blockIdx.x * 128;
    const int wm0 = (wid >> 2) * 64;
    const int wn0 = (wid & 3) * 32;

    // output routing
    float* C;
    int ldc, cbase;
    bool rnd = true;
    if (csel == 4) {
        if (n0 < 2048)      { C = g_Q; ldc = DM;  cbase = n0; }
        else if (n0 < 2560) { C = g_K; ldc = KVD; cbase = n0 - 2048; }
        else                { C = g_V; ldc = KVD; cbase = n0 - 2560; }
    } else {
        C = Cext; ldc = DM; cbase = n0; rnd = false;
    }

    // ldmatrix lane roles
    const int lt = lane & 7;
    const int tt = lane >> 3;
    const int arow = wm0 + lt + (tt & 1) * 8;
    const int acol = (tt >> 1) * 4;
    const int brow = wn0 + lt + (tt >> 1) * 8;
    const int bcol = (tt & 1) * 4;

    float c[4][4][4];
#pragma unroll
    for (int mt = 0; mt < 4; mt++)
#pragma unroll
        for (int nt = 0; nt < 4; nt++)
#pragma unroll
            for (int i = 0; i < 4; i++) c[mt][nt][i] = 0.f;

    const int nk = K / 32;

    auto issue = [&](int kt, int buf) {
        const uint32_t abase = sb + buf * STG_FLT * 4;
        const uint32_t bbase = abase + 128 * ASTRIDE * 4;
        const int k0 = kt * 32;
#pragma unroll
        for (int i = 0; i < 4; i++) {
            int idx = tid + i * 256;
            int row = idx >> 3;
            int ch = idx & 7;
            cp_async16(abase + (row * ASTRIDE + ch * 4) * 4,
                       &A[(size_t)(m0 + row) * K + k0 + ch * 4]);
            cp_async16(bbase + (row * ASTRIDE + ch * 4) * 4,
                       &W[(size_t)(n0 + row) * K + k0 + ch * 4]);
        }
        cp_commit();
    };

    issue(0, 0);
    issue(1, 1);

    int buf = 0;          // stage holding tile kt
    int wbuf = 2;         // stage to fill with tile kt+2
    for (int kt = 0; kt < nk; kt++) {
        cp_wait<1>();
        __syncthreads();          // tile kt ready; all threads done reading stage wbuf

        if (kt + 2 < nk) issue(kt + 2, wbuf);
        else cp_commit();         // keep wait-group accounting uniform

        const uint32_t stg = sb + buf * STG_FLT * 4;
        const uint32_t a_base = stg + (arow * ASTRIDE + acol) * 4;
        const uint32_t b_base = stg + 128 * ASTRIDE * 4 + (brow * ASTRIDE + bcol) * 4;

#pragma unroll
        for (int ks = 0; ks < 4; ks++) {
            uint32_t a[4][4], b[2][4];
#pragma unroll
            for (int mt = 0; mt < 4; mt++)
                ldsm_x4(a[mt], a_base + (mt * 16 * ASTRIDE + ks * 8) * 4);
#pragma unroll
            for (int np = 0; np < 2; np++)
                ldsm_x4(b[np], b_base + (np * 16 * ASTRIDE + ks * 8) * 4);
#pragma unroll
            for (int mt = 0; mt < 4; mt++)
#pragma unroll
                for (int nt = 0; nt < 4; nt++)
                    mma_tf32(c[mt][nt], a[mt], &b[nt >> 1][(nt & 1) * 2]);
        }
        buf = (buf == 2) ? 0 : buf + 1;
        wbuf = (wbuf == 2) ? 0 : wbuf + 1;
    }

#pragma unroll
    for (int mt = 0; mt < 4; mt++) {
        const int r0 = m0 + wm0 + mt * 16 + (lane >> 2);
#pragma unroll
        for (int nt = 0; nt < 4; nt++) {
            const int col = cbase + wn0 + nt * 8 + (lane & 3) * 2;
            float v0 = c[mt][nt][0], v1 = c[mt][nt][1];
            float v2 = c[mt][nt][2], v3 = c[mt][nt][3];
            if (rnd) {
                v0 = f2tf32f(v0); v1 = f2tf32f(v1);
                v2 = f2tf32f(v2); v3 = f2tf32f(v3);
            }
            *(float2*)&C[(size_t)r0 * ldc + col] = make_float2(v0, v1);
            *(float2*)&C[(size_t)(r0 + 8) * ldc + col] = make_float2(v2, v3);
        }
    }
}

// ---------------------------------------------------------------------------
// Tensor-core causal GQA flash attention (tf32 mma, fp32 softmax).
// CTA: (qt, b*32+h); 256 threads = 8 warps; BQ=128 (16 q-rows/warp), BKV=64.
// cp.async double-buffered K (plain pad, ldmatrix frags) + V (raw rows,
// stride 72, scalar frags). Heaviest q-tiles launch first.
// ---------------------------------------------------------------------------
#define PAD   68
#define VPAD  72
#define KS_FL (64 * PAD)     // 4352 floats per K buffer
#define VR_FL (64 * VPAD)    // 4608 floats per V buffer
#define ATTN_SMEM ((2 * KS_FL + 2 * VR_FL + 128 * PAD) * 4)   // 106496 B

__global__ __launch_bounds__(256, 2) void gqa_attn_tc()
{
    extern __shared__ float asm_[];
    float* Ks = asm_;                   // 2 x [64][PAD]
    float* Vr = Ks + 2 * KS_FL;         // 2 x [64][VPAD]
    float* Pt = Vr + 2 * VR_FL;         // [128][PAD]
    const uint32_t sb = smem_u32(asm_);
    const uint32_t sbK = sb;
    const uint32_t sbV = sb + 2 * KS_FL * 4;

    const int tid = threadIdx.x;
    const int w = tid >> 5;
    const int lane = tid & 31;
    const int r = lane >> 2;
    const int cb = lane & 3;
    const int qt = (int)gridDim.x - 1 - (int)blockIdx.x;   // heavy tiles first
    const int bh = blockIdx.y;
    const int b = bh >> 5, h = bh & 31, g = h >> 2;
    const int q0 = qt * 128;
    const int wrow = w * 16;

    // ldmatrix lane roles for K B-frags
    const int lt = lane & 7;
    const int tt = lane >> 3;
    const int kbrow = lt + (tt >> 1) * 8;   // n(kv) row within 16-row pair
    const int kbcol = (tt & 1) * 4;         // d offset

    const float* Qb = g_Q + (size_t)b * SQ * DM + h * HDIM;
    const float* Kb = g_K + (size_t)b * SQ * KVD + g * HDIM;
    const float* Vb = g_V + (size_t)b * SQ * KVD + g * HDIM;

    // Stage Q (x 0.125 exact; inputs already tf32-rounded) into Pt
#pragma unroll
    for (int i = 0; i < 8; i++) {
        int idx = tid + i * 256;
        int row = idx >> 4, ch = idx & 15;
        float4 v = *(const float4*)&Qb[(size_t)(q0 + row) * DM + ch * 4];
        float* dst = &Pt[row * PAD + ch * 4];
        dst[0] = v.x * 0.125f;
        dst[1] = v.y * 0.125f;
        dst[2] = v.z * 0.125f;
        dst[3] = v.w * 0.125f;
    }
    __syncthreads();

    uint32_t qf[8][4];
#pragma unroll
    for (int ks = 0; ks < 8; ks++) {
        qf[ks][0] = __float_as_uint(Pt[(wrow + r) * PAD + ks * 8 + cb]);
        qf[ks][1] = __float_as_uint(Pt[(wrow + 8 + r) * PAD + ks * 8 + cb]);
        qf[ks][2] = __float_as_uint(Pt[(wrow + r) * PAD + ks * 8 + cb + 4]);
        qf[ks][3] = __float_as_uint(Pt[(wrow + 8 + r) * PAD + ks * 8 + cb + 4]);
    }
    __syncthreads();

    float of[8][4];
#pragma unroll
    for (int dt = 0; dt < 8; dt++)
#pragma unroll
        for (int i = 0; i < 4; i++) of[dt][i] = 0.f;
    float m0r = -1e30f, m1r = -1e30f, l0 = 0.f, l1 = 0.f;

    const int nkt = qt * 2 + 2;

    auto issue_tile = [&](int kt) {
        const int buf = kt & 1;
        const uint32_t kbuf = sbK + buf * KS_FL * 4;
        const uint32_t vbuf = sbV + buf * VR_FL * 4;
        const int k0 = kt * 64;
#pragma unroll
        for (int i = 0; i < 4; i++) {
            int idx = tid + i * 256;
            int kk = idx >> 4, ch = idx & 15;
            cp_async16(kbuf + (kk * PAD + ch * 4) * 4,
                       &Kb[(size_t)(k0 + kk) * KVD + ch * 4]);
            cp_async16(vbuf + (kk * VPAD + ch * 4) * 4,
                       &Vb[(size_t)(k0 + kk) * KVD + ch * 4]);
        }
        cp_commit();
    };

    issue_tile(0);

    for (int kt = 0; kt < nkt; kt++) {
        if (kt + 1 < nkt) {
            issue_tile(kt + 1);
            cp_wait<1>();
        } else {
            cp_wait<0>();
        }
        __syncthreads();

        const uint32_t kBufA = sbK + (kt & 1) * KS_FL * 4 + (kbrow * PAD + kbcol) * 4;
        const float* VrT = Vr + (kt & 1) * VR_FL;
        const int k0 = kt * 64;

        const bool active = (k0 <= q0 + wrow + 15);
        if (active) {
            float sf[8][4];
#pragma unroll
            for (int nt = 0; nt < 8; nt++)
#pragma unroll
                for (int i = 0; i < 4; i++) sf[nt][i] = 0.f;
#pragma unroll
            for (int ks = 0; ks < 8; ks++) {
                uint32_t bf[4][4];
#pragma unroll
                for (int np = 0; np < 4; np++)
                    ldsm_x4(bf[np], kBufA + (np * 16 * PAD + ks * 8) * 4);
#pragma unroll
                for (int nt = 0; nt < 8; nt++)
                    mma_tf32(sf[nt], qf[ks], &bf[nt >> 1][(nt & 1) * 2]);
            }
            if (k0 + 63 > q0 + wrow) {
                const int qr0 = q0 + wrow + r;
                const int qr1 = qr0 + 8;
#pragma unroll
                for (int nt = 0; nt < 8; nt++) {
                    const int kvc = k0 + nt * 8 + cb * 2;
                    if (kvc > qr0)     sf[nt][0] = -1e30f;
                    if (kvc + 1 > qr0) sf[nt][1] = -1e30f;
                    if (kvc > qr1)     sf[nt][2] = -1e30f;
                    if (kvc + 1 > qr1) sf[nt][3] = -1e30f;
                }
            }
            float mx0 = m0r, mx1 = m1r;
#pragma unroll
            for (int nt = 0; nt < 8; nt++) {
                mx0 = fmaxf(mx0, fmaxf(sf[nt][0], sf[nt][1]));
                mx1 = fmaxf(mx1, fmaxf(sf[nt][2], sf[nt][3]));
            }
            mx0 = fmaxf(mx0, __shfl_xor_sync(0xffffffffu, mx0, 1));
            mx0 = fmaxf(mx0, __shfl_xor_sync(0xffffffffu, mx0, 2));
            mx1 = fmaxf(mx1, __shfl_xor_sync(0xffffffffu, mx1, 1));
            mx1 = fmaxf(mx1, __shfl_xor_sync(0xffffffffu, mx1, 2));
            const float a0 = __expf(m0r - mx0), a1 = __expf(m1r - mx1);
            m0r = mx0; m1r = mx1;
            float s0 = 0.f, s1 = 0.f;
#pragma unroll
            for (int nt = 0; nt < 8; nt++) {
                float p00 = __expf(sf[nt][0] - mx0);
                float p01 = __expf(sf[nt][1] - mx0);
                float p10 = __expf(sf[nt][2] - mx1);
                float p11 = __expf(sf[nt][3] - mx1);
                s0 += p00 + p01; s1 += p10 + p11;
                *(float2*)&Pt[(wrow + r) * PAD + nt * 8 + cb * 2] =
                    make_float2(f2tf32f(p00), f2tf32f(p01));
                *(float2*)&Pt[(wrow + 8 + r) * PAD + nt * 8 + cb * 2] =
                    make_float2(f2tf32f(p10), f2tf32f(p11));
            }
            s0 += __shfl_xor_sync(0xffffffffu, s0, 1);
            s0 += __shfl_xor_sync(0xffffffffu, s0, 2);
            s1 += __shfl_xor_sync(0xffffffffu, s1, 1);
            s1 += __shfl_xor_sync(0xffffffffu, s1, 2);
            l0 = l0 * a0 + s0;
            l1 = l1 * a1 + s1;
#pragma unroll
            for (int dt = 0; dt < 8; dt++) {
                of[dt][0] *= a0; of[dt][1] *= a0;
                of[dt][2] *= a1; of[dt][3] *= a1;
            }
            __syncwarp();
            // O += P.V  (B frags straight from raw V rows)
#pragma unroll
            for (int ks = 0; ks < 8; ks++) {
                uint32_t a[4];
                a[0] = __float_as_uint(Pt[(wrow + r) * PAD + ks * 8 + cb]);
                a[1] = __float_as_uint(Pt[(wrow + 8 + r) * PAD + ks * 8 + cb]);
                a[2] = __float_as_uint(Pt[(wrow + r) * PAD + ks * 8 + cb + 4]);
                a[3] = __float_as_uint(Pt[(wrow + 8 + r) * PAD + ks * 8 + cb + 4]);
                const float* vrow = &VrT[(ks * 8 + cb) * VPAD + r];
#pragma unroll
                for (int dt = 0; dt < 8; dt++) {
                    uint32_t bb[2] = { __float_as_uint(vrow[dt * 8]),
                                       __float_as_uint(vrow[4 * VPAD + dt * 8]) };
                    mma_tf32(of[dt], a, bb);
                }
            }
        }
        __syncthreads();
    }

    // epilogue: write ctx tf32-rounded (final GEMM reads it raw)
    const float i0 = 1.f / l0, i1 = 1.f / l1;
    float* C0 = g_C + ((size_t)b * SQ + q0 + wrow + r) * DM + h * HDIM;
    float* C1 = C0 + 8 * DM;
#pragma unroll
    for (int dt = 0; dt < 8; dt++) {
        const int col = dt * 8 + cb * 2;
        *(float2*)&C0[col] = make_float2(f2tf32f(of[dt][0] * i0), f2tf32f(of[dt][1] * i0));
        *(float2*)&C1[col] = make_float2(f2tf32f(of[dt][2] * i1), f2tf32f(of[dt][3] * i1));
    }
}

// ---------------------------------------------------------------------------
extern "C" void kernel_launch(void* const* d_in, const int* in_sizes, int n_in,
                              void* d_out, int out_size)
{
    (void)in_sizes; (void)n_in; (void)out_size;
    const float* x  = (const float*)d_in[0];
    const float* Wq = (const float*)d_in[1];
    const float* Wk = (const float*)d_in[2];
    const float* Wv = (const float*)d_in[3];
    const float* Wo = (const float*)d_in[4];
    float* out = (float*)d_out;

    const int M = BATCH * SQ;   // 4096

    cudaFuncSetAttribute(gemm_tc32, cudaFuncAttributeMaxDynamicSharedMemorySize, GEMM_SMEM);
    cudaFuncSetAttribute(gqa_attn_tc, cudaFuncAttributeMaxDynamicSharedMemorySize, ATTN_SMEM);

    float* xt; cudaGetSymbolAddress((void**)&xt, g_Xt);
    float* wt; cudaGetSymbolAddress((void**)&wt, g_Wt);

    // Pre-convert x and weights to tf32 bit patterns (rna, once)
    {
        int n4 = (int)((size_t)M * DM / 4);
        cvt_tf32_k<<<(n4 + 255) / 256, 256>>>((const float4*)x, (float4*)xt, n4);
        n4 = DM * DM / 4;
        cvt_tf32_k<<<(n4 + 255) / 256, 256>>>((const float4*)Wq, (float4*)(wt + WQ_OFF), n4);
        n4 = KVD * DM / 4;
        cvt_tf32_k<<<(n4 + 255) / 256, 256>>>((const float4*)Wk, (float4*)(wt + WK_OFF), n4);
        cvt_tf32_k<<<(n4 + 255) / 256, 256>>>((const float4*)Wv, (float4*)(wt + WV_OFF), n4);
        n4 = DM * DM / 4;
        cvt_tf32_k<<<(n4 + 255) / 256, 256>>>((const float4*)Wo, (float4*)(wt + WO_OFF), n4);
    }

    // Fused Q|K|V = x @ [Wq;Wk;Wv]^T   (3072 weight rows, contiguous)
    gemm_tc32<<<dim3(3072 / 128, M / 128), 256, GEMM_SMEM>>>(0, 0, 4, nullptr, M, DM);
    // Causal GQA attention -> g_C
    gqa_attn_tc<<<dim3(SQ / 128, BATCH * NH), 256, ATTN_SMEM>>>();
    // out = ctx @ Wo^T
    gemm_tc32<<<dim3(DM / 128, M / 128), 256, GEMM_SMEM>>>(1, WO_OFF, 3, out, M, DM);
}

// round 10
// speedup vs baseline: 1.3182x; 1.0154x over previous
#include <cuda_runtime.h>
#include <math.h>
#include <stdint.h>

// Problem constants
#define BATCH 2
#define SQ    2048
#define DM    2048     // model dim
#define KVD   512      // G*HD
#define NH    32       // heads
#define HDIM  64       // head dim

// Scratch (allocation-free rule: __device__ globals)
__device__ float g_Q[(size_t)BATCH * SQ * DM];   // tf32-rounded
__device__ float g_K[(size_t)BATCH * SQ * KVD];  // tf32-rounded
__device__ float g_V[(size_t)BATCH * SQ * KVD];  // tf32-rounded
__device__ float g_C[(size_t)BATCH * SQ * DM];   // ctx, tf32-rounded
__device__ float g_Xt[(size_t)BATCH * SQ * DM];  // x, tf32-rounded
// packed tf32 weights: Wq | Wk | Wv | Wo  (QKV contiguous -> fused GEMM)
#define WQ_OFF 0
#define WK_OFF (2048 * 2048)
#define WV_OFF (WK_OFF + 512 * 2048)
#define WO_OFF (WV_OFF + 512 * 2048)
__device__ float g_Wt[WO_OFF + 2048 * 2048];

// ---------------------------------------------------------------------------
// helpers
// ---------------------------------------------------------------------------
__device__ __forceinline__ uint32_t smem_u32(const void* p) {
    uint32_t a;
    asm("{ .reg .u64 t; cvta.to.shared.u64 t, %1; cvt.u32.u64 %0, t; }"
        : "=r"(a) : "l"(p));
    return a;
}
__device__ __forceinline__ void cp_async16(uint32_t dst, const void* src) {
    asm volatile("cp.async.cg.shared.global [%0], [%1], 16;" :: "r"(dst), "l"(src));
}
__device__ __forceinline__ void cp_commit() {
    asm volatile("cp.async.commit_group;" ::: "memory");
}
template <int N>
__device__ __forceinline__ void cp_wait() {
    asm volatile("cp.async.wait_group %0;" :: "n"(N) : "memory");
}
__device__ __forceinline__ uint32_t f2tf32(float f) {
    uint32_t r;
    asm("cvt.rna.tf32.f32 %0, %1;" : "=r"(r) : "f"(f));
    return r;
}
__device__ __forceinline__ float f2tf32f(float f) {
    return __uint_as_float(f2tf32(f));
}
__device__ __forceinline__ void mma_tf32(float* c, const uint32_t* a, const uint32_t* b) {
    asm volatile(
        "mma.sync.aligned.m16n8k8.row.col.f32.tf32.tf32.f32 "
        "{%0,%1,%2,%3}, {%4,%5,%6,%7}, {%8,%9}, {%0,%1,%2,%3};"
        : "+f"(c[0]), "+f"(c[1]), "+f"(c[2]), "+f"(c[3])
        : "r"(a[0]), "r"(a[1]), "r"(a[2]), "r"(a[3]), "r"(b[0]), "r"(b[1]));
}
__device__ __forceinline__ void ldsm_x4(uint32_t* r, uint32_t addr) {
    asm volatile("ldmatrix.sync.aligned.m8n8.x4.shared.b16 {%0,%1,%2,%3}, [%4];"
                 : "=r"(r[0]), "=r"(r[1]), "=r"(r[2]), "=r"(r[3]) : "r"(addr));
}

// ---------------------------------------------------------------------------
// Fused one-shot fp32 -> tf32-bits conversion for x + all four weights.
// Dst layout is contiguous (g_Xt, then g_Wt = Wq|Wk|Wv|Wo) -> single sweep.
// ---------------------------------------------------------------------------
#define N4_X ((BATCH * SQ * DM) / 4)     // 2097152
#define N4_Q ((DM * DM) / 4)             // 1048576
#define N4_K ((KVD * DM) / 4)            // 262144
#define N4_TOTAL (N4_X + 2 * N4_Q + 2 * N4_K)

__global__ __launch_bounds__(256) void cvt_all(
    const float4* __restrict__ x,  const float4* __restrict__ wq,
    const float4* __restrict__ wk, const float4* __restrict__ wv,
    const float4* __restrict__ wo, float4* __restrict__ xt,
    float4* __restrict__ wt)
{
    int i = blockIdx.x * 256 + threadIdx.x;
    if (i >= N4_TOTAL) return;
    const float4* s;
    float4* d;
    if (i < N4_X) { s = x + i; d = xt + i; }
    else {
        int j = i - N4_X;
        d = wt + j;
        if (j < N4_Q)                   s = wq + j;
        else if (j < N4_Q + N4_K)       s = wk + (j - N4_Q);
        else if (j < N4_Q + 2 * N4_K)   s = wv + (j - N4_Q - N4_K);
        else                            s = wo + (j - N4_Q - 2 * N4_K);
    }
    float4 v = *s;
    *d = make_float4(f2tf32f(v.x), f2tf32f(v.y), f2tf32f(v.z), f2tf32f(v.w));
}

// ---------------------------------------------------------------------------
// TF32 mma.sync GEMM on pre-converted data:  C[M,N] = A[M,K] . W[N,K]^T
// CTA: 128x128 tile, BK=32, 256 threads (8 warps, 2m x 4n; warp tile 64x32).
// 3-stage cp.async pipeline, ONE __syncthreads per k-tile. ldmatrix frags.
// csel: 3=Cext (raw), 4=fused QKV (route by n0, tf32-rounded)
// ---------------------------------------------------------------------------
#define ASTRIDE 36
#define STG_FLT (2 * 128 * ASTRIDE)         // floats per stage (A + B) = 9216
#define GEMM_SMEM (3 * STG_FLT * 4)         // 110592 bytes

__global__ __launch_bounds__(256, 2) void gemm_tc32(
    int asel, int woff, int csel, float* __restrict__ Cext, int M, int K)
{
    extern __shared__ float sm[];
    const uint32_t sb = smem_u32(sm);
    const float* A = asel ? g_C : g_Xt;
    const float* W = g_Wt + woff;

    const int tid = threadIdx.x;
    const int wid = tid >> 5;
    const int lane = tid & 31;
    const int m0 = blockIdx.y * 128;
    const int n0 = blockIdx.x * 128;
    const int wm0 = (wid >> 2) * 64;
    const int wn0 = (wid & 3) * 32;

    // output routing
    float* C;
    int ldc, cbase;
    bool rnd = true;
    if (csel == 4) {
        if (n0 < 2048)      { C = g_Q; ldc = DM;  cbase = n0; }
        else if (n0 < 2560) { C = g_K; ldc = KVD; cbase = n0 - 2048; }
        else                { C = g_V; ldc = KVD; cbase = n0 - 2560; }
    } else {
        C = Cext; ldc = DM; cbase = n0; rnd = false;
    }

    // ldmatrix lane roles
    const int lt = lane & 7;
    const int tt = lane >> 3;
    const int arow = wm0 + lt + (tt & 1) * 8;
    const int acol = (tt >> 1) * 4;
    const int brow = wn0 + lt + (tt >> 1) * 8;
    const int bcol = (tt & 1) * 4;

    float c[4][4][4];
#pragma unroll
    for (int mt = 0; mt < 4; mt++)
#pragma unroll
        for (int nt = 0; nt < 4; nt++)
#pragma unroll
            for (int i = 0; i < 4; i++) c[mt][nt][i] = 0.f;

    const int nk = K / 32;

    auto issue = [&](int kt, int buf) {
        const uint32_t abase = sb + buf * STG_FLT * 4;
        const uint32_t bbase = abase + 128 * ASTRIDE * 4;
        const int k0 = kt * 32;
#pragma unroll
        for (int i = 0; i < 4; i++) {
            int idx = tid + i * 256;
            int row = idx >> 3;
            int ch = idx & 7;
            cp_async16(abase + (row * ASTRIDE + ch * 4) * 4,
                       &A[(size_t)(m0 + row) * K + k0 + ch * 4]);
            cp_async16(bbase + (row * ASTRIDE + ch * 4) * 4,
                       &W[(size_t)(n0 + row) * K + k0 + ch * 4]);
        }
        cp_commit();
    };

    issue(0, 0);
    issue(1, 1);

    int buf = 0;          // stage holding tile kt
    int wbuf = 2;         // stage to fill with tile kt+2
    for (int kt = 0; kt < nk; kt++) {
        cp_wait<1>();
        __syncthreads();          // tile kt ready; all threads done reading stage wbuf

        if (kt + 2 < nk) issue(kt + 2, wbuf);
        else cp_commit();         // keep wait-group accounting uniform

        const uint32_t stg = sb + buf * STG_FLT * 4;
        const uint32_t a_base = stg + (arow * ASTRIDE + acol) * 4;
        const uint32_t b_base = stg + 128 * ASTRIDE * 4 + (brow * ASTRIDE + bcol) * 4;

#pragma unroll
        for (int ks = 0; ks < 4; ks++) {
            uint32_t a[4][4], b[2][4];
#pragma unroll
            for (int mt = 0; mt < 4; mt++)
                ldsm_x4(a[mt], a_base + (mt * 16 * ASTRIDE + ks * 8) * 4);
#pragma unroll
            for (int np = 0; np < 2; np++)
                ldsm_x4(b[np], b_base + (np * 16 * ASTRIDE + ks * 8) * 4);
#pragma unroll
            for (int mt = 0; mt < 4; mt++)
#pragma unroll
                for (int nt = 0; nt < 4; nt++)
                    mma_tf32(c[mt][nt], a[mt], &b[nt >> 1][(nt & 1) * 2]);
        }
        buf = (buf == 2) ? 0 : buf + 1;
        wbuf = (wbuf == 2) ? 0 : wbuf + 1;
    }

#pragma unroll
    for (int mt = 0; mt < 4; mt++) {
        const int r0 = m0 + wm0 + mt * 16 + (lane >> 2);
#pragma unroll
        for (int nt = 0; nt < 4; nt++) {
            const int col = cbase + wn0 + nt * 8 + (lane & 3) * 2;
            float v0 = c[mt][nt][0], v1 = c[mt][nt][1];
            float v2 = c[mt][nt][2], v3 = c[mt][nt][3];
            if (rnd) {
                v0 = f2tf32f(v0); v1 = f2tf32f(v1);
                v2 = f2tf32f(v2); v3 = f2tf32f(v3);
            }
            *(float2*)&C[(size_t)r0 * ldc + col] = make_float2(v0, v1);
            *(float2*)&C[(size_t)(r0 + 8) * ldc + col] = make_float2(v2, v3);
        }
    }
}

// ---------------------------------------------------------------------------
// Tensor-core causal GQA flash attention (tf32 mma, fp32 softmax).
// CTA: (qt, b*32+h); 256 threads = 8 warps; BQ=128 (16 q-rows/warp), BKV=64.
// cp.async double-buffered K/V with ONE __syncthreads per kv-tile:
//   wait(kt) -> sync (publishes kt AND closes WAR on buf kt-1) -> issue(kt+1)
//   -> compute(kt).  Heaviest q-tiles launch first.
// ---------------------------------------------------------------------------
#define PAD   68
#define VPAD  72
#define KS_FL (64 * PAD)     // 4352 floats per K buffer
#define VR_FL (64 * VPAD)    // 4608 floats per V buffer
#define ATTN_SMEM ((2 * KS_FL + 2 * VR_FL + 128 * PAD) * 4)   // 106496 B

__global__ __launch_bounds__(256, 2) void gqa_attn_tc()
{
    extern __shared__ float asm_[];
    float* Ks = asm_;                   // 2 x [64][PAD]
    float* Vr = Ks + 2 * KS_FL;         // 2 x [64][VPAD]
    float* Pt = Vr + 2 * VR_FL;         // [128][PAD]
    const uint32_t sb = smem_u32(asm_);
    const uint32_t sbK = sb;
    const uint32_t sbV = sb + 2 * KS_FL * 4;

    const int tid = threadIdx.x;
    const int w = tid >> 5;
    const int lane = tid & 31;
    const int r = lane >> 2;
    const int cb = lane & 3;
    const int qt = (int)gridDim.x - 1 - (int)blockIdx.x;   // heavy tiles first
    const int bh = blockIdx.y;
    const int b = bh >> 5, h = bh & 31, g = h >> 2;
    const int q0 = qt * 128;
    const int wrow = w * 16;

    // ldmatrix lane roles for K B-frags
    const int lt = lane & 7;
    const int tt = lane >> 3;
    const int kbrow = lt + (tt >> 1) * 8;
    const int kbcol = (tt & 1) * 4;

    const float* Qb = g_Q + (size_t)b * SQ * DM + h * HDIM;
    const float* Kb = g_K + (size_t)b * SQ * KVD + g * HDIM;
    const float* Vb = g_V + (size_t)b * SQ * KVD + g * HDIM;

    // Stage Q (x 0.125 exact; inputs already tf32-rounded) into Pt
#pragma unroll
    for (int i = 0; i < 8; i++) {
        int idx = tid + i * 256;
        int row = idx >> 4, ch = idx & 15;
        float4 v = *(const float4*)&Qb[(size_t)(q0 + row) * DM + ch * 4];
        float* dst = &Pt[row * PAD + ch * 4];
        dst[0] = v.x * 0.125f;
        dst[1] = v.y * 0.125f;
        dst[2] = v.z * 0.125f;
        dst[3] = v.w * 0.125f;
    }
    __syncthreads();

    uint32_t qf[8][4];
#pragma unroll
    for (int ks = 0; ks < 8; ks++) {
        qf[ks][0] = __float_as_uint(Pt[(wrow + r) * PAD + ks * 8 + cb]);
        qf[ks][1] = __float_as_uint(Pt[(wrow + 8 + r) * PAD + ks * 8 + cb]);
        qf[ks][2] = __float_as_uint(Pt[(wrow + r) * PAD + ks * 8 + cb + 4]);
        qf[ks][3] = __float_as_uint(Pt[(wrow + 8 + r) * PAD + ks * 8 + cb + 4]);
    }
    __syncthreads();

    float of[8][4];
#pragma unroll
    for (int dt = 0; dt < 8; dt++)
#pragma unroll
        for (int i = 0; i < 4; i++) of[dt][i] = 0.f;
    float m0r = -1e30f, m1r = -1e30f, l0 = 0.f, l1 = 0.f;

    const int nkt = qt * 2 + 2;

    auto issue_tile = [&](int kt) {
        const int buf = kt & 1;
        const uint32_t kbuf = sbK + buf * KS_FL * 4;
        const uint32_t vbuf = sbV + buf * VR_FL * 4;
        const int k0 = kt * 64;
#pragma unroll
        for (int i = 0; i < 4; i++) {
            int idx = tid + i * 256;
            int kk = idx >> 4, ch = idx & 15;
            cp_async16(kbuf + (kk * PAD + ch * 4) * 4,
                       &Kb[(size_t)(k0 + kk) * KVD + ch * 4]);
            cp_async16(vbuf + (kk * VPAD + ch * 4) * 4,
                       &Vb[(size_t)(k0 + kk) * KVD + ch * 4]);
        }
        cp_commit();
    };

    issue_tile(0);

    for (int kt = 0; kt < nkt; kt++) {
        cp_wait<0>();             // own copies of tile kt complete
        __syncthreads();          // publish tile kt; compute(kt-1) reads all done

        if (kt + 1 < nkt) issue_tile(kt + 1);   // fills buf (kt+1)&1 == (kt-1)&1

        const uint32_t kBufA = sbK + (kt & 1) * KS_FL * 4 + (kbrow * PAD + kbcol) * 4;
        const float* VrT = Vr + (kt & 1) * VR_FL;
        const int k0 = kt * 64;

        const bool active = (k0 <= q0 + wrow + 15);
        if (active) {
            float sf[8][4];
#pragma unroll
            for (int nt = 0; nt < 8; nt++)
#pragma unroll
                for (int i = 0; i < 4; i++) sf[nt][i] = 0.f;
#pragma unroll
            for (int ks = 0; ks < 8; ks++) {
                uint32_t bf[4][4];
#pragma unroll
                for (int np = 0; np < 4; np++)
                    ldsm_x4(bf[np], kBufA + (np * 16 * PAD + ks * 8) * 4);
#pragma unroll
                for (int nt = 0; nt < 8; nt++)
                    mma_tf32(sf[nt], qf[ks], &bf[nt >> 1][(nt & 1) * 2]);
            }
            if (k0 + 63 > q0 + wrow) {
                const int qr0 = q0 + wrow + r;
                const int qr1 = qr0 + 8;
#pragma unroll
                for (int nt = 0; nt < 8; nt++) {
                    const int kvc = k0 + nt * 8 + cb * 2;
                    if (kvc > qr0)     sf[nt][0] = -1e30f;
                    if (kvc + 1 > qr0) sf[nt][1] = -1e30f;
                    if (kvc > qr1)     sf[nt][2] = -1e30f;
                    if (kvc + 1 > qr1) sf[nt][3] = -1e30f;
                }
            }
            float mx0 = m0r, mx1 = m1r;
#pragma unroll
            for (int nt = 0; nt < 8; nt++) {
                mx0 = fmaxf(mx0, fmaxf(sf[nt][0], sf[nt][1]));
                mx1 = fmaxf(mx1, fmaxf(sf[nt][2], sf[nt][3]));
            }
            mx0 = fmaxf(mx0, __shfl_xor_sync(0xffffffffu, mx0, 1));
            mx0 = fmaxf(mx0, __shfl_xor_sync(0xffffffffu, mx0, 2));
            mx1 = fmaxf(mx1, __shfl_xor_sync(0xffffffffu, mx1, 1));
            mx1 = fmaxf(mx1, __shfl_xor_sync(0xffffffffu, mx1, 2));
            const float a0 = __expf(m0r - mx0), a1 = __expf(m1r - mx1);
            m0r = mx0; m1r = mx1;
            float s0 = 0.f, s1 = 0.f;
#pragma unroll
            for (int nt = 0; nt < 8; nt++) {
                float p00 = __expf(sf[nt][0] - mx0);
                float p01 = __expf(sf[nt][1] - mx0);
                float p10 = __expf(sf[nt][2] - mx1);
                float p11 = __expf(sf[nt][3] - mx1);
                s0 += p00 + p01; s1 += p10 + p11;
                *(float2*)&Pt[(wrow + r) * PAD + nt * 8 + cb * 2] =
                    make_float2(f2tf32f(p00), f2tf32f(p01));
                *(float2*)&Pt[(wrow + 8 + r) * PAD + nt * 8 + cb * 2] =
                    make_float2(f2tf32f(p10), f2tf32f(p11));
            }
            s0 += __shfl_xor_sync(0xffffffffu, s0, 1);
            s0 += __shfl_xor_sync(0xffffffffu, s0, 2);
            s1 += __shfl_xor_sync(0xffffffffu, s1, 1);
            s1 += __shfl_xor_sync(0xffffffffu, s1, 2);
            l0 = l0 * a0 + s0;
            l1 = l1 * a1 + s1;
#pragma unroll
            for (int dt = 0; dt < 8; dt++) {
                of[dt][0] *= a0; of[dt][1] *= a0;
                of[dt][2] *= a1; of[dt][3] *= a1;
            }
            __syncwarp();
            // O += P.V  (B frags straight from raw V rows)
#pragma unroll
            for (int ks = 0; ks < 8; ks++) {
                uint32_t a[4];
                a[0] = __float_as_uint(Pt[(wrow + r) * PAD + ks * 8 + cb]);
                a[1] = __float_as_uint(Pt[(wrow + 8 + r) * PAD + ks * 8 + cb]);
                a[2] = __float_as_uint(Pt[(wrow + r) * PAD + ks * 8 + cb + 4]);
                a[3] = __float_as_uint(Pt[(wrow + 8 + r) * PAD + ks * 8 + cb + 4]);
                const float* vrow = &VrT[(ks * 8 + cb) * VPAD + r];
#pragma unroll
                for (int dt = 0; dt < 8; dt++) {
                    uint32_t bb[2] = { __float_as_uint(vrow[dt * 8]),
                                       __float_as_uint(vrow[4 * VPAD + dt * 8]) };
                    mma_tf32(of[dt], a, bb);
                }
            }
        }
    }

    // epilogue: write ctx tf32-rounded (final GEMM reads it raw)
    const float i0 = 1.f / l0, i1 = 1.f / l1;
    float* C0 = g_C + ((size_t)b * SQ + q0 + wrow + r) * DM + h * HDIM;
    float* C1 = C0 + 8 * DM;
#pragma unroll
    for (int dt = 0; dt < 8; dt++) {
        const int col = dt * 8 + cb * 2;
        *(float2*)&C0[col] = make_float2(f2tf32f(of[dt][0] * i0), f2tf32f(of[dt][1] * i0));
        *(float2*)&C1[col] = make_float2(f2tf32f(of[dt][2] * i1), f2tf32f(of[dt][3] * i1));
    }
}

// ---------------------------------------------------------------------------
extern "C" void kernel_launch(void* const* d_in, const int* in_sizes, int n_in,
                              void* d_out, int out_size)
{
    (void)in_sizes; (void)n_in; (void)out_size;
    const float* x  = (const float*)d_in[0];
    const float* Wq = (const float*)d_in[1];
    const float* Wk = (const float*)d_in[2];
    const float* Wv = (const float*)d_in[3];
    const float* Wo = (const float*)d_in[4];
    float* out = (float*)d_out;

    const int M = BATCH * SQ;   // 4096

    cudaFuncSetAttribute(gemm_tc32, cudaFuncAttributeMaxDynamicSharedMemorySize, GEMM_SMEM);
    cudaFuncSetAttribute(gqa_attn_tc, cudaFuncAttributeMaxDynamicSharedMemorySize, ATTN_SMEM);

    float* xt; cudaGetSymbolAddress((void**)&xt, g_Xt);
    float* wt; cudaGetSymbolAddress((void**)&wt, g_Wt);

    // Pre-convert x and all weights to tf32 bit patterns (rna) in ONE launch
    cvt_all<<<(N4_TOTAL + 255) / 256, 256>>>(
        (const float4*)x, (const float4*)Wq, (const float4*)Wk,
        (const float4*)Wv, (const float4*)Wo, (float4*)xt, (float4*)wt);

    // Fused Q|K|V = x @ [Wq;Wk;Wv]^T   (3072 weight rows, contiguous)
    gemm_tc32<<<dim3(3072 / 128, M / 128), 256, GEMM_SMEM>>>(0, 0, 4, nullptr, M, DM);
    // Causal GQA attention -> g_C
    gqa_attn_tc<<<dim3(SQ / 128, BATCH * NH), 256, ATTN_SMEM>>>();
    // out = ctx @ Wo^T
    gemm_tc32<<<dim3(DM / 128, M / 128), 256, GEMM_SMEM>>>(1, WO_OFF, 3, out, M, DM);
}

// round 11
// speedup vs baseline: 1.3771x; 1.0447x over previous
#include <cuda_runtime.h>
#include <math.h>
#include <stdint.h>

// Problem constants
#define BATCH 2
#define SQ    2048
#define DM    2048     // model dim
#define KVD   512      // G*HD
#define NH    32       // heads
#define HDIM  64       // head dim

// Scratch (allocation-free rule: __device__ globals)
__device__ float g_Q[(size_t)BATCH * SQ * DM];   // tf32-rounded
__device__ float g_K[(size_t)BATCH * SQ * KVD];  // tf32-rounded
__device__ float g_V[(size_t)BATCH * SQ * KVD];  // tf32-rounded
__device__ float g_C[(size_t)BATCH * SQ * DM];   // ctx, tf32-rounded
__device__ float g_Xt[(size_t)BATCH * SQ * DM];  // x, tf32-rounded
// packed tf32 weights: Wq | Wk | Wv | Wo  (QKV contiguous -> fused GEMM)
#define WQ_OFF 0
#define WK_OFF (2048 * 2048)
#define WV_OFF (WK_OFF + 512 * 2048)
#define WO_OFF (WV_OFF + 512 * 2048)
__device__ float g_Wt[WO_OFF + 2048 * 2048];

// ---------------------------------------------------------------------------
// helpers
// ---------------------------------------------------------------------------
__device__ __forceinline__ uint32_t smem_u32(const void* p) {
    uint32_t a;
    asm("{ .reg .u64 t; cvta.to.shared.u64 t, %1; cvt.u32.u64 %0, t; }"
        : "=r"(a) : "l"(p));
    return a;
}
__device__ __forceinline__ void cp_async16(uint32_t dst, const void* src) {
    asm volatile("cp.async.cg.shared.global [%0], [%1], 16;" :: "r"(dst), "l"(src));
}
__device__ __forceinline__ void cp_commit() {
    asm volatile("cp.async.commit_group;" ::: "memory");
}
template <int N>
__device__ __forceinline__ void cp_wait() {
    asm volatile("cp.async.wait_group %0;" :: "n"(N) : "memory");
}
__device__ __forceinline__ uint32_t f2tf32(float f) {
    uint32_t r;
    asm("cvt.rna.tf32.f32 %0, %1;" : "=r"(r) : "f"(f));
    return r;
}
__device__ __forceinline__ float f2tf32f(float f) {
    return __uint_as_float(f2tf32(f));
}
__device__ __forceinline__ void mma_tf32(float* c, const uint32_t* a, const uint32_t* b) {
    asm volatile(
        "mma.sync.aligned.m16n8k8.row.col.f32.tf32.tf32.f32 "
        "{%0,%1,%2,%3}, {%4,%5,%6,%7}, {%8,%9}, {%0,%1,%2,%3};"
        : "+f"(c[0]), "+f"(c[1]), "+f"(c[2]), "+f"(c[3])
        : "r"(a[0]), "r"(a[1]), "r"(a[2]), "r"(a[3]), "r"(b[0]), "r"(b[1]));
}
__device__ __forceinline__ void ldsm_x4(uint32_t* r, uint32_t addr) {
    asm volatile("ldmatrix.sync.aligned.m8n8.x4.shared.b16 {%0,%1,%2,%3}, [%4];"
                 : "=r"(r[0]), "=r"(r[1]), "=r"(r[2]), "=r"(r[3]) : "r"(addr));
}

// ---------------------------------------------------------------------------
// Fused one-shot fp32 -> tf32-bits conversion for x + all four weights.
// ---------------------------------------------------------------------------
#define N4_X ((BATCH * SQ * DM) / 4)     // 2097152
#define N4_Q ((DM * DM) / 4)             // 1048576
#define N4_K ((KVD * DM) / 4)            // 262144
#define N4_TOTAL (N4_X + 2 * N4_Q + 2 * N4_K)

__global__ __launch_bounds__(256) void cvt_all(
    const float4* __restrict__ x,  const float4* __restrict__ wq,
    const float4* __restrict__ wk, const float4* __restrict__ wv,
    const float4* __restrict__ wo, float4* __restrict__ xt,
    float4* __restrict__ wt)
{
    int i = blockIdx.x * 256 + threadIdx.x;
    if (i >= N4_TOTAL) return;
    const float4* s;
    float4* d;
    if (i < N4_X) { s = x + i; d = xt + i; }
    else {
        int j = i - N4_X;
        d = wt + j;
        if (j < N4_Q)                   s = wq + j;
        else if (j < N4_Q + N4_K)       s = wk + (j - N4_Q);
        else if (j < N4_Q + 2 * N4_K)   s = wv + (j - N4_Q - N4_K);
        else                            s = wo + (j - N4_Q - 2 * N4_K);
    }
    float4 v = *s;
    *d = make_float4(f2tf32f(v.x), f2tf32f(v.y), f2tf32f(v.z), f2tf32f(v.w));
}

// ---------------------------------------------------------------------------
// TF32 mma.sync GEMM on pre-converted data:  C[M,N] = A[M,K] . W[N,K]^T
// CTA: 128x128 tile, BK=32, 256 threads (8 warps, 2m x 4n; warp tile 64x32).
// 3-stage cp.async, ONE __syncthreads per k-tile; prefetch issued after the
// ks=0 MMA block so the post-barrier window is pure LDSM+MMA ramp.
// ---------------------------------------------------------------------------
#define ASTRIDE 36
#define STG_FLT (2 * 128 * ASTRIDE)         // floats per stage (A + B) = 9216
#define GEMM_SMEM (3 * STG_FLT * 4)         // 110592 bytes

__global__ __launch_bounds__(256, 2) void gemm_tc32(
    int asel, int woff, int csel, float* __restrict__ Cext, int M, int K)
{
    extern __shared__ float sm[];
    const uint32_t sb = smem_u32(sm);
    const float* A = asel ? g_C : g_Xt;
    const float* W = g_Wt + woff;

    const int tid = threadIdx.x;
    const int wid = tid >> 5;
    const int lane = tid & 31;
    const int m0 = blockIdx.y * 128;
    const int n0 = blockIdx.x * 128;
    const int wm0 = (wid >> 2) * 64;
    const int wn0 = (wid & 3) * 32;

    // output routing
    float* C;
    int ldc, cbase;
    bool rnd = true;
    if (csel == 4) {
        if (n0 < 2048)      { C = g_Q; ldc = DM;  cbase = n0; }
        else if (n0 < 2560) { C = g_K; ldc = KVD; cbase = n0 - 2048; }
        else                { C = g_V; ldc = KVD; cbase = n0 - 2560; }
    } else {
        C = Cext; ldc = DM; cbase = n0; rnd = false;
    }

    // ldmatrix lane roles
    const int lt = lane & 7;
    const int tt = lane >> 3;
    const int arow = wm0 + lt + (tt & 1) * 8;
    const int acol = (tt >> 1) * 4;
    const int brow = wn0 + lt + (tt >> 1) * 8;
    const int bcol = (tt & 1) * 4;

    float c[4][4][4];
#pragma unroll
    for (int mt = 0; mt < 4; mt++)
#pragma unroll
        for (int nt = 0; nt < 4; nt++)
#pragma unroll
            for (int i = 0; i < 4; i++) c[mt][nt][i] = 0.f;

    const int nk = K / 32;

    auto issue = [&](int kt, int buf) {
        const uint32_t abase = sb + buf * STG_FLT * 4;
        const uint32_t bbase = abase + 128 * ASTRIDE * 4;
        const int k0 = kt * 32;
#pragma unroll
        for (int i = 0; i < 4; i++) {
            int idx = tid + i * 256;
            int row = idx >> 3;
            int ch = idx & 7;
            cp_async16(abase + (row * ASTRIDE + ch * 4) * 4,
                       &A[(size_t)(m0 + row) * K + k0 + ch * 4]);
            cp_async16(bbase + (row * ASTRIDE + ch * 4) * 4,
                       &W[(size_t)(n0 + row) * K + k0 + ch * 4]);
        }
        cp_commit();
    };

    issue(0, 0);
    issue(1, 1);

    int buf = 0;          // stage holding tile kt
    int wbuf = 2;         // stage to fill with tile kt+2
    for (int kt = 0; kt < nk; kt++) {
        cp_wait<1>();
        __syncthreads();          // tile kt ready; all reads of stage wbuf done

        const uint32_t stg = sb + buf * STG_FLT * 4;
        const uint32_t a_base = stg + (arow * ASTRIDE + acol) * 4;
        const uint32_t b_base = stg + 128 * ASTRIDE * 4 + (brow * ASTRIDE + bcol) * 4;

#pragma unroll
        for (int ks = 0; ks < 4; ks++) {
            uint32_t a[4][4], b[2][4];
#pragma unroll
            for (int mt = 0; mt < 4; mt++)
                ldsm_x4(a[mt], a_base + (mt * 16 * ASTRIDE + ks * 8) * 4);
#pragma unroll
            for (int np = 0; np < 2; np++)
                ldsm_x4(b[np], b_base + (np * 16 * ASTRIDE + ks * 8) * 4);
#pragma unroll
            for (int mt = 0; mt < 4; mt++)
#pragma unroll
                for (int nt = 0; nt < 4; nt++)
                    mma_tf32(c[mt][nt], a[mt], &b[nt >> 1][(nt & 1) * 2]);

            if (ks == 0) {                     // prefetch after ramp-up
                if (kt + 2 < nk) issue(kt + 2, wbuf);
                else cp_commit();
            }
        }
        buf = (buf == 2) ? 0 : buf + 1;
        wbuf = (wbuf == 2) ? 0 : wbuf + 1;
    }

#pragma unroll
    for (int mt = 0; mt < 4; mt++) {
        const int r0 = m0 + wm0 + mt * 16 + (lane >> 2);
#pragma unroll
        for (int nt = 0; nt < 4; nt++) {
            const int col = cbase + wn0 + nt * 8 + (lane & 3) * 2;
            float v0 = c[mt][nt][0], v1 = c[mt][nt][1];
            float v2 = c[mt][nt][2], v3 = c[mt][nt][3];
            if (rnd) {
                v0 = f2tf32f(v0); v1 = f2tf32f(v1);
                v2 = f2tf32f(v2); v3 = f2tf32f(v3);
            }
            *(float2*)&C[(size_t)r0 * ldc + col] = make_float2(v0, v1);
            *(float2*)&C[(size_t)(r0 + 8) * ldc + col] = make_float2(v2, v3);
        }
    }
}

// ---------------------------------------------------------------------------
// Tensor-core causal GQA flash attention (tf32 mma, fp32 softmax).
// CTA: (qt, b*32+h); 256 threads = 8 warps; BQ=128 (16 q-rows/warp), BKV=64.
// cp.async double-buffered K/V, ONE __syncthreads per kv-tile; prefetch of
// tile kt+1 issued AFTER the QK MMA loop. Q and P fragments via ldmatrix
// (Pt stride 68 -> phase banks 4r mod 32, conflict-free).
// ---------------------------------------------------------------------------
#define PAD   68
#define VPAD  72
#define KS_FL (64 * PAD)     // 4352 floats per K buffer
#define VR_FL (64 * VPAD)    // 4608 floats per V buffer
#define ATTN_SMEM ((2 * KS_FL + 2 * VR_FL + 128 * PAD) * 4)   // 106496 B

__global__ __launch_bounds__(256, 2) void gqa_attn_tc()
{
    extern __shared__ float asm_[];
    float* Vr = asm_ + 2 * KS_FL;       // 2 x [64][VPAD]
    float* Pt = Vr + 2 * VR_FL;         // [128][PAD]
    const uint32_t sb = smem_u32(asm_);
    const uint32_t sbK = sb;
    const uint32_t sbV = sb + 2 * KS_FL * 4;
    const uint32_t sbP = sbV + 2 * VR_FL * 4;

    const int tid = threadIdx.x;
    const int w = tid >> 5;
    const int lane = tid & 31;
    const int r = lane >> 2;
    const int cb = lane & 3;
    const int qt = (int)gridDim.x - 1 - (int)blockIdx.x;   // heavy tiles first
    const int bh = blockIdx.y;
    const int b = bh >> 5, h = bh & 31, g = h >> 2;
    const int q0 = qt * 128;
    const int wrow = w * 16;

    // ldmatrix lane roles (A-pattern for Q/P, B-pattern for K)
    const int lt = lane & 7;
    const int tt = lane >> 3;
    const int parow = wrow + lt + (tt & 1) * 8;   // A-frag row in Pt
    const int pacol = (tt >> 1) * 4;              // A-frag col offset
    const int kbrow = lt + (tt >> 1) * 8;         // B-frag kv row
    const int kbcol = (tt & 1) * 4;               // B-frag d offset

    const float* Qb = g_Q + (size_t)b * SQ * DM + h * HDIM;
    const float* Kb = g_K + (size_t)b * SQ * KVD + g * HDIM;
    const float* Vb = g_V + (size_t)b * SQ * KVD + g * HDIM;

    // Stage Q (x 0.125 exact; inputs already tf32-rounded) into Pt
#pragma unroll
    for (int i = 0; i < 8; i++) {
        int idx = tid + i * 256;
        int row = idx >> 4, ch = idx & 15;
        float4 v = *(const float4*)&Qb[(size_t)(q0 + row) * DM + ch * 4];
        float* dst = &Pt[row * PAD + ch * 4];
        dst[0] = v.x * 0.125f;
        dst[1] = v.y * 0.125f;
        dst[2] = v.z * 0.125f;
        dst[3] = v.w * 0.125f;
    }
    __syncthreads();

    const uint32_t pA = sbP + (parow * PAD + pacol) * 4;
    uint32_t qf[8][4];
#pragma unroll
    for (int ks = 0; ks < 8; ks++)
        ldsm_x4(qf[ks], pA + ks * 8 * 4);
    __syncthreads();

    float of[8][4];
#pragma unroll
    for (int dt = 0; dt < 8; dt++)
#pragma unroll
        for (int i = 0; i < 4; i++) of[dt][i] = 0.f;
    float m0r = -1e30f, m1r = -1e30f, l0 = 0.f, l1 = 0.f;

    const int nkt = qt * 2 + 2;

    auto issue_tile = [&](int kt) {
        const int buf = kt & 1;
        const uint32_t kbuf = sbK + buf * KS_FL * 4;
        const uint32_t vbuf = sbV + buf * VR_FL * 4;
        const int k0 = kt * 64;
#pragma unroll
        for (int i = 0; i < 4; i++) {
            int idx = tid + i * 256;
            int kk = idx >> 4, ch = idx & 15;
            cp_async16(kbuf + (kk * PAD + ch * 4) * 4,
                       &Kb[(size_t)(k0 + kk) * KVD + ch * 4]);
            cp_async16(vbuf + (kk * VPAD + ch * 4) * 4,
                       &Vb[(size_t)(k0 + kk) * KVD + ch * 4]);
        }
        cp_commit();
    };

    issue_tile(0);

    for (int kt = 0; kt < nkt; kt++) {
        cp_wait<0>();             // own copies of tile kt complete
        __syncthreads();          // publish tile kt; compute(kt-1) reads done

        const uint32_t kBufA = sbK + (kt & 1) * KS_FL * 4 + (kbrow * PAD + kbcol) * 4;
        const float* VrT = Vr + (kt & 1) * VR_FL;
        const int k0 = kt * 64;

        const bool active = (k0 <= q0 + wrow + 15);
        float sf[8][4];
        if (active) {
#pragma unroll
            for (int nt = 0; nt < 8; nt++)
#pragma unroll
                for (int i = 0; i < 4; i++) sf[nt][i] = 0.f;
#pragma unroll
            for (int ks = 0; ks < 8; ks++) {
                uint32_t bf[4][4];
#pragma unroll
                for (int np = 0; np < 4; np++)
                    ldsm_x4(bf[np], kBufA + (np * 16 * PAD + ks * 8) * 4);
#pragma unroll
                for (int nt = 0; nt < 8; nt++)
                    mma_tf32(sf[nt], qf[ks], &bf[nt >> 1][(nt & 1) * 2]);
            }
        }

        if (kt + 1 < nkt) issue_tile(kt + 1);   // prefetch after QK phase

        if (active) {
            if (k0 + 63 > q0 + wrow) {
                const int qr0 = q0 + wrow + r;
                const int qr1 = qr0 + 8;
#pragma unroll
                for (int nt = 0; nt < 8; nt++) {
                    const int kvc = k0 + nt * 8 + cb * 2;
                    if (kvc > qr0)     sf[nt][0] = -1e30f;
                    if (kvc + 1 > qr0) sf[nt][1] = -1e30f;
                    if (kvc > qr1)     sf[nt][2] = -1e30f;
                    if (kvc + 1 > qr1) sf[nt][3] = -1e30f;
                }
            }
            float mx0 = m0r, mx1 = m1r;
#pragma unroll
            for (int nt = 0; nt < 8; nt++) {
                mx0 = fmaxf(mx0, fmaxf(sf[nt][0], sf[nt][1]));
                mx1 = fmaxf(mx1, fmaxf(sf[nt][2], sf[nt][3]));
            }
            mx0 = fmaxf(mx0, __shfl_xor_sync(0xffffffffu, mx0, 1));
            mx0 = fmaxf(mx0, __shfl_xor_sync(0xffffffffu, mx0, 2));
            mx1 = fmaxf(mx1, __shfl_xor_sync(0xffffffffu, mx1, 1));
            mx1 = fmaxf(mx1, __shfl_xor_sync(0xffffffffu, mx1, 2));
            const float a0 = __expf(m0r - mx0), a1 = __expf(m1r - mx1);
            m0r = mx0; m1r = mx1;
            float s0 = 0.f, s1 = 0.f;
#pragma unroll
            for (int nt = 0; nt < 8; nt++) {
                float p00 = __expf(sf[nt][0] - mx0);
                float p01 = __expf(sf[nt][1] - mx0);
                float p10 = __expf(sf[nt][2] - mx1);
                float p11 = __expf(sf[nt][3] - mx1);
                s0 += p00 + p01; s1 += p10 + p11;
                *(float2*)&Pt[(wrow + r) * PAD + nt * 8 + cb * 2] =
                    make_float2(f2tf32f(p00), f2tf32f(p01));
                *(float2*)&Pt[(wrow + 8 + r) * PAD + nt * 8 + cb * 2] =
                    make_float2(f2tf32f(p10), f2tf32f(p11));
            }
            s0 += __shfl_xor_sync(0xffffffffu, s0, 1);
            s0 += __shfl_xor_sync(0xffffffffu, s0, 2);
            s1 += __shfl_xor_sync(0xffffffffu, s1, 1);
            s1 += __shfl_xor_sync(0xffffffffu, s1, 2);
            l0 = l0 * a0 + s0;
            l1 = l1 * a1 + s1;
#pragma unroll
            for (int dt = 0; dt < 8; dt++) {
                of[dt][0] *= a0; of[dt][1] *= a0;
                of[dt][2] *= a1; of[dt][3] *= a1;
            }
            __syncwarp();
            // O += P.V  (A frags via ldmatrix on Pt; B from raw V rows)
#pragma unroll
            for (int ks = 0; ks < 8; ks++) {
                uint32_t a[4];
                ldsm_x4(a, pA + ks * 8 * 4);
                const float* vrow = &VrT[(ks * 8 + cb) * VPAD + r];
#pragma unroll
                for (int dt = 0; dt < 8; dt++) {
                    uint32_t bb[2] = { __float_as_uint(vrow[dt * 8]),
                                       __float_as_uint(vrow[4 * VPAD + dt * 8]) };
                    mma_tf32(of[dt], a, bb);
                }
            }
        }
    }

    // epilogue: write ctx tf32-rounded (final GEMM reads it raw)
    const float i0 = 1.f / l0, i1 = 1.f / l1;
    float* C0 = g_C + ((size_t)b * SQ + q0 + wrow + r) * DM + h * HDIM;
    float* C1 = C0 + 8 * DM;
#pragma unroll
    for (int dt = 0; dt < 8; dt++) {
        const int col = dt * 8 + cb * 2;
        *(float2*)&C0[col] = make_float2(f2tf32f(of[dt][0] * i0), f2tf32f(of[dt][1] * i0));
        *(float2*)&C1[col] = make_float2(f2tf32f(of[dt][2] * i1), f2tf32f(of[dt][3] * i1));
    }
}

// ---------------------------------------------------------------------------
extern "C" void kernel_launch(void* const* d_in, const int* in_sizes, int n_in,
                              void* d_out, int out_size)
{
    (void)in_sizes; (void)n_in; (void)out_size;
    const float* x  = (const float*)d_in[0];
    const float* Wq = (const float*)d_in[1];
    const float* Wk = (const float*)d_in[2];
    const float* Wv = (const float*)d_in[3];
    const float* Wo = (const float*)d_in[4];
    float* out = (float*)d_out;

    const int M = BATCH * SQ;   // 4096

    cudaFuncSetAttribute(gemm_tc32, cudaFuncAttributeMaxDynamicSharedMemorySize, GEMM_SMEM);
    cudaFuncSetAttribute(gqa_attn_tc, cudaFuncAttributeMaxDynamicSharedMemorySize, ATTN_SMEM);

    float* xt; cudaGetSymbolAddress((void**)&xt, g_Xt);
    float* wt; cudaGetSymbolAddress((void**)&wt, g_Wt);

    // Pre-convert x and all weights to tf32 bit patterns (rna) in ONE launch
    cvt_all<<<(N4_TOTAL + 255) / 256, 256>>>(
        (const float4*)x, (const float4*)Wq, (const float4*)Wk,
        (const float4*)Wv, (const float4*)Wo, (float4*)xt, (float4*)wt);

    // Fused Q|K|V = x @ [Wq;Wk;Wv]^T   (3072 weight rows, contiguous)
    gemm_tc32<<<dim3(3072 / 128, M / 128), 256, GEMM_SMEM>>>(0, 0, 4, nullptr, M, DM);
    // Causal GQA attention -> g_C
    gqa_attn_tc<<<dim3(SQ / 128, BATCH * NH), 256, ATTN_SMEM>>>();
    // out = ctx @ Wo^T
    gemm_tc32<<<dim3(DM / 128, M / 128), 256, GEMM_SMEM>>>(1, WO_OFF, 3, out, M, DM);
}

// round 12
// speedup vs baseline: 1.3957x; 1.0135x over previous
#include <cuda_runtime.h>
#include <math.h>
#include <stdint.h>

// Problem constants
#define BATCH 2
#define SQ    2048
#define DM    2048     // model dim
#define KVD   512      // G*HD
#define NH    32       // heads
#define NG    8        // kv groups
#define HDIM  64       // head dim

// Scratch (allocation-free rule: __device__ globals)
__device__ float g_Q[(size_t)BATCH * SQ * DM];   // tf32-rounded
__device__ float g_K[(size_t)BATCH * SQ * KVD];  // tf32-rounded
__device__ float g_V[(size_t)BATCH * SQ * KVD];  // tf32-rounded, TRANSPOSED: [b][g][d][s]
__device__ float g_C[(size_t)BATCH * SQ * DM];   // ctx, tf32-rounded
__device__ float g_Xt[(size_t)BATCH * SQ * DM];  // x, tf32-rounded
// packed tf32 weights: Wq | Wk | Wv | Wo  (QKV contiguous -> fused GEMM)
#define WQ_OFF 0
#define WK_OFF (2048 * 2048)
#define WV_OFF (WK_OFF + 512 * 2048)
#define WO_OFF (WV_OFF + 512 * 2048)
__device__ float g_Wt[WO_OFF + 2048 * 2048];

// ---------------------------------------------------------------------------
// helpers
// ---------------------------------------------------------------------------
__device__ __forceinline__ uint32_t smem_u32(const void* p) {
    uint32_t a;
    asm("{ .reg .u64 t; cvta.to.shared.u64 t, %1; cvt.u32.u64 %0, t; }"
        : "=r"(a) : "l"(p));
    return a;
}
__device__ __forceinline__ void cp_async16(uint32_t dst, const void* src) {
    asm volatile("cp.async.cg.shared.global [%0], [%1], 16;" :: "r"(dst), "l"(src));
}
__device__ __forceinline__ void cp_commit() {
    asm volatile("cp.async.commit_group;" ::: "memory");
}
template <int N>
__device__ __forceinline__ void cp_wait() {
    asm volatile("cp.async.wait_group %0;" :: "n"(N) : "memory");
}
__device__ __forceinline__ uint32_t f2tf32(float f) {
    uint32_t r;
    asm("cvt.rna.tf32.f32 %0, %1;" : "=r"(r) : "f"(f));
    return r;
}
__device__ __forceinline__ float f2tf32f(float f) {
    return __uint_as_float(f2tf32(f));
}
__device__ __forceinline__ void mma_tf32(float* c, const uint32_t* a, const uint32_t* b) {
    asm volatile(
        "mma.sync.aligned.m16n8k8.row.col.f32.tf32.tf32.f32 "
        "{%0,%1,%2,%3}, {%4,%5,%6,%7}, {%8,%9}, {%0,%1,%2,%3};"
        : "+f"(c[0]), "+f"(c[1]), "+f"(c[2]), "+f"(c[3])
        : "r"(a[0]), "r"(a[1]), "r"(a[2]), "r"(a[3]), "r"(b[0]), "r"(b[1]));
}
__device__ __forceinline__ void ldsm_x4(uint32_t* r, uint32_t addr) {
    asm volatile("ldmatrix.sync.aligned.m8n8.x4.shared.b16 {%0,%1,%2,%3}, [%4];"
                 : "=r"(r[0]), "=r"(r[1]), "=r"(r[2]), "=r"(r[3]) : "r"(addr));
}

// ---------------------------------------------------------------------------
// Fused one-shot fp32 -> tf32-bits conversion for x + all four weights.
// ---------------------------------------------------------------------------
#define N4_X ((BATCH * SQ * DM) / 4)     // 2097152
#define N4_Q ((DM * DM) / 4)             // 1048576
#define N4_K ((KVD * DM) / 4)            // 262144
#define N4_TOTAL (N4_X + 2 * N4_Q + 2 * N4_K)

__global__ __launch_bounds__(256) void cvt_all(
    const float4* __restrict__ x,  const float4* __restrict__ wq,
    const float4* __restrict__ wk, const float4* __restrict__ wv,
    const float4* __restrict__ wo, float4* __restrict__ xt,
    float4* __restrict__ wt)
{
    int i = blockIdx.x * 256 + threadIdx.x;
    if (i >= N4_TOTAL) return;
    const float4* s;
    float4* d;
    if (i < N4_X) { s = x + i; d = xt + i; }
    else {
        int j = i - N4_X;
        d = wt + j;
        if (j < N4_Q)                   s = wq + j;
        else if (j < N4_Q + N4_K)       s = wk + (j - N4_Q);
        else if (j < N4_Q + 2 * N4_K)   s = wv + (j - N4_Q - N4_K);
        else                            s = wo + (j - N4_Q - 2 * N4_K);
    }
    float4 v = *s;
    *d = make_float4(f2tf32f(v.x), f2tf32f(v.y), f2tf32f(v.z), f2tf32f(v.w));
}

// ---------------------------------------------------------------------------
// TF32 mma.sync GEMM on pre-converted data:  C[M,N] = A[M,K] . W[N,K]^T
// CTA: 128x128 tile, BK=32, 256 threads (8 warps, 2m x 4n; warp tile 64x32).
// 3-stage cp.async, ONE __syncthreads per k-tile; prefetch after ks=0 MMAs.
// V output (csel 4, n0>=2560) stored TRANSPOSED into g_V [b][g][d][s].
// ---------------------------------------------------------------------------
#define ASTRIDE 36
#define STG_FLT (2 * 128 * ASTRIDE)         // floats per stage (A + B) = 9216
#define GEMM_SMEM (3 * STG_FLT * 4)         // 110592 bytes

__global__ __launch_bounds__(256, 2) void gemm_tc32(
    int asel, int woff, int csel, float* __restrict__ Cext, int M, int K)
{
    extern __shared__ float sm[];
    const uint32_t sb = smem_u32(sm);
    const float* A = asel ? g_C : g_Xt;
    const float* W = g_Wt + woff;

    const int tid = threadIdx.x;
    const int wid = tid >> 5;
    const int lane = tid & 31;
    const int m0 = blockIdx.y * 128;
    const int n0 = blockIdx.x * 128;
    const int wm0 = (wid >> 2) * 64;
    const int wn0 = (wid & 3) * 32;

    // output routing
    float* C = Cext;
    int ldc = DM, cbase = n0;
    bool rnd = true, vtrans = false;
    if (csel == 4) {
        if (n0 < 2048)      { C = g_Q; ldc = DM;  cbase = n0; }
        else if (n0 < 2560) { C = g_K; ldc = KVD; cbase = n0 - 2048; }
        else                { C = g_V; vtrans = true; cbase = n0 - 2560; }
    } else {
        rnd = false;
    }

    // ldmatrix lane roles
    const int lt = lane & 7;
    const int tt = lane >> 3;
    const int arow = wm0 + lt + (tt & 1) * 8;
    const int acol = (tt >> 1) * 4;
    const int brow = wn0 + lt + (tt >> 1) * 8;
    const int bcol = (tt & 1) * 4;

    float c[4][4][4];
#pragma unroll
    for (int mt = 0; mt < 4; mt++)
#pragma unroll
        for (int nt = 0; nt < 4; nt++)
#pragma unroll
            for (int i = 0; i < 4; i++) c[mt][nt][i] = 0.f;

    const int nk = K / 32;

    auto issue = [&](int kt, int buf) {
        const uint32_t abase = sb + buf * STG_FLT * 4;
        const uint32_t bbase = abase + 128 * ASTRIDE * 4;
        const int k0 = kt * 32;
#pragma unroll
        for (int i = 0; i < 4; i++) {
            int idx = tid + i * 256;
            int row = idx >> 3;
            int ch = idx & 7;
            cp_async16(abase + (row * ASTRIDE + ch * 4) * 4,
                       &A[(size_t)(m0 + row) * K + k0 + ch * 4]);
            cp_async16(bbase + (row * ASTRIDE + ch * 4) * 4,
                       &W[(size_t)(n0 + row) * K + k0 + ch * 4]);
        }
        cp_commit();
    };

    issue(0, 0);
    issue(1, 1);

    int buf = 0;
    int wbuf = 2;
    for (int kt = 0; kt < nk; kt++) {
        cp_wait<1>();
        __syncthreads();

        const uint32_t stg = sb + buf * STG_FLT * 4;
        const uint32_t a_base = stg + (arow * ASTRIDE + acol) * 4;
        const uint32_t b_base = stg + 128 * ASTRIDE * 4 + (brow * ASTRIDE + bcol) * 4;

#pragma unroll
        for (int ks = 0; ks < 4; ks++) {
            uint32_t a[4][4], b[2][4];
#pragma unroll
            for (int mt = 0; mt < 4; mt++)
                ldsm_x4(a[mt], a_base + (mt * 16 * ASTRIDE + ks * 8) * 4);
#pragma unroll
            for (int np = 0; np < 2; np++)
                ldsm_x4(b[np], b_base + (np * 16 * ASTRIDE + ks * 8) * 4);
#pragma unroll
            for (int mt = 0; mt < 4; mt++)
#pragma unroll
                for (int nt = 0; nt < 4; nt++)
                    mma_tf32(c[mt][nt], a[mt], &b[nt >> 1][(nt & 1) * 2]);

            if (ks == 0) {
                if (kt + 2 < nk) issue(kt + 2, wbuf);
                else cp_commit();
            }
        }
        buf = (buf == 2) ? 0 : buf + 1;
        wbuf = (wbuf == 2) ? 0 : wbuf + 1;
    }

#pragma unroll
    for (int mt = 0; mt < 4; mt++) {
        const int r0 = m0 + wm0 + mt * 16 + (lane >> 2);
#pragma unroll
        for (int nt = 0; nt < 4; nt++) {
            const int col = cbase + wn0 + nt * 8 + (lane & 3) * 2;
            float v0 = c[mt][nt][0], v1 = c[mt][nt][1];
            float v2 = c[mt][nt][2], v3 = c[mt][nt][3];
            if (rnd) {
                v0 = f2tf32f(v0); v1 = f2tf32f(v1);
                v2 = f2tf32f(v2); v3 = f2tf32f(v3);
            }
            if (vtrans) {
                // V^T layout: g_V[((b*NG+g)*HDIM + d) * SQ + s]
                const int bb = r0 >> 11, s = r0 & 2047;
                const int gg = col >> 6, d = col & 63;
                float* base = C + ((size_t)(bb * NG + gg) * HDIM + d) * SQ + s;
                base[0] = v0;                    // (d,   s)
                base[SQ] = v1;                   // (d+1, s)
                base[8] = v2;                    // (d,   s+8)
                base[SQ + 8] = v3;               // (d+1, s+8)
            } else {
                *(float2*)&C[(size_t)r0 * ldc + col] = make_float2(v0, v1);
                *(float2*)&C[(size_t)(r0 + 8) * ldc + col] = make_float2(v2, v3);
            }
        }
    }
}

// ---------------------------------------------------------------------------
// Tensor-core causal GQA flash attention (tf32 mma, fp32 softmax).
// CTA: (qt, b*32+h); 256 threads = 8 warps; BQ=128 (16 q-rows/warp), BKV=64.
// K AND V (pre-transposed, d-major) tiles via cp.async double buffer; both
// consumed with ldmatrix B-frags. P/Q A-frags via ldmatrix on Pt.
// ONE __syncthreads per kv-tile; prefetch after QK MMA phase.
// ---------------------------------------------------------------------------
#define PAD   68
#define TS_FL (64 * PAD)     // 4352 floats per K or V buffer
#define ATTN_SMEM ((4 * TS_FL + 128 * PAD) * 4)   // 104448 B

__global__ __launch_bounds__(256, 2) void gqa_attn_tc()
{
    extern __shared__ float asm_[];
    float* Pt = asm_ + 4 * TS_FL;       // [128][PAD]
    const uint32_t sb = smem_u32(asm_);
    const uint32_t sbK = sb;
    const uint32_t sbV = sb + 2 * TS_FL * 4;
    const uint32_t sbP = sb + 4 * TS_FL * 4;

    const int tid = threadIdx.x;
    const int w = tid >> 5;
    const int lane = tid & 31;
    const int r = lane >> 2;
    const int cb = lane & 3;
    const int qt = (int)gridDim.x - 1 - (int)blockIdx.x;   // heavy tiles first
    const int bh = blockIdx.y;
    const int b = bh >> 5, h = bh & 31, g = h >> 2;
    const int q0 = qt * 128;
    const int wrow = w * 16;

    // ldmatrix lane roles (A-pattern for Q/P, B-pattern for K/V)
    const int lt = lane & 7;
    const int tt = lane >> 3;
    const int parow = wrow + lt + (tt & 1) * 8;
    const int pacol = (tt >> 1) * 4;
    const int nbrow = lt + (tt >> 1) * 8;     // B-frag n row (kv for K, d for V)
    const int nbcol = (tt & 1) * 4;           // B-frag k col

    const float* Qb = g_Q + (size_t)b * SQ * DM + h * HDIM;
    const float* Kb = g_K + (size_t)b * SQ * KVD + g * HDIM;
    const float* Vb = g_V + (size_t)(b * NG + g) * HDIM * SQ;   // [d][s]

    // Stage Q (x 0.125 exact; inputs already tf32-rounded) into Pt
#pragma unroll
    for (int i = 0; i < 8; i++) {
        int idx = tid + i * 256;
        int row = idx >> 4, ch = idx & 15;
        float4 v = *(const float4*)&Qb[(size_t)(q0 + row) * DM + ch * 4];
        float* dst = &Pt[row * PAD + ch * 4];
        dst[0] = v.x * 0.125f;
        dst[1] = v.y * 0.125f;
        dst[2] = v.z * 0.125f;
        dst[3] = v.w * 0.125f;
    }
    __syncthreads();

    const uint32_t pA = sbP + (parow * PAD + pacol) * 4;
    uint32_t qf[8][4];
#pragma unroll
    for (int ks = 0; ks < 8; ks++)
        ldsm_x4(qf[ks], pA + ks * 8 * 4);
    __syncthreads();

    float of[8][4];
#pragma unroll
    for (int dt = 0; dt < 8; dt++)
#pragma unroll
        for (int i = 0; i < 4; i++) of[dt][i] = 0.f;
    float m0r = -1e30f, m1r = -1e30f, l0 = 0.f, l1 = 0.f;

    const int nkt = qt * 2 + 2;

    auto issue_tile = [&](int kt) {
        const int buf = kt & 1;
        const uint32_t kbuf = sbK + buf * TS_FL * 4;
        const uint32_t vbuf = sbV + buf * TS_FL * 4;
        const int k0 = kt * 64;
#pragma unroll
        for (int i = 0; i < 4; i++) {
            int idx = tid + i * 256;
            int row = idx >> 4, ch = idx & 15;        // K: row=kv; V: row=d
            cp_async16(kbuf + (row * PAD + ch * 4) * 4,
                       &Kb[(size_t)(k0 + row) * KVD + ch * 4]);
            cp_async16(vbuf + (row * PAD + ch * 4) * 4,
                       &Vb[(size_t)row * SQ + k0 + ch * 4]);
        }
        cp_commit();
    };

    issue_tile(0);

    for (int kt = 0; kt < nkt; kt++) {
        cp_wait<0>();
        __syncthreads();

        const uint32_t kBufA = sbK + (kt & 1) * TS_FL * 4 + (nbrow * PAD + nbcol) * 4;
        const uint32_t vBufA = sbV + (kt & 1) * TS_FL * 4 + (nbrow * PAD + nbcol) * 4;
        const int k0 = kt * 64;

        const bool active = (k0 <= q0 + wrow + 15);
        float sf[8][4];
        if (active) {
#pragma unroll
            for (int nt = 0; nt < 8; nt++)
#pragma unroll
                for (int i = 0; i < 4; i++) sf[nt][i] = 0.f;
#pragma unroll
            for (int ks = 0; ks < 8; ks++) {
                uint32_t bf[4][4];
#pragma unroll
                for (int np = 0; np < 4; np++)
                    ldsm_x4(bf[np], kBufA + (np * 16 * PAD + ks * 8) * 4);
#pragma unroll
                for (int nt = 0; nt < 8; nt++)
                    mma_tf32(sf[nt], qf[ks], &bf[nt >> 1][(nt & 1) * 2]);
            }
        }

        if (kt + 1 < nkt) issue_tile(kt + 1);

        if (active) {
            if (k0 + 63 > q0 + wrow) {
                const int qr0 = q0 + wrow + r;
                const int qr1 = qr0 + 8;
#pragma unroll
                for (int nt = 0; nt < 8; nt++) {
                    const int kvc = k0 + nt * 8 + cb * 2;
                    if (kvc > qr0)     sf[nt][0] = -1e30f;
                    if (kvc + 1 > qr0) sf[nt][1] = -1e30f;
                    if (kvc > qr1)     sf[nt][2] = -1e30f;
                    if (kvc + 1 > qr1) sf[nt][3] = -1e30f;
                }
            }
            float mx0 = m0r, mx1 = m1r;
#pragma unroll
            for (int nt = 0; nt < 8; nt++) {
                mx0 = fmaxf(mx0, fmaxf(sf[nt][0], sf[nt][1]));
                mx1 = fmaxf(mx1, fmaxf(sf[nt][2], sf[nt][3]));
            }
            mx0 = fmaxf(mx0, __shfl_xor_sync(0xffffffffu, mx0, 1));
            mx0 = fmaxf(mx0, __shfl_xor_sync(0xffffffffu, mx0, 2));
            mx1 = fmaxf(mx1, __shfl_xor_sync(0xffffffffu, mx1, 1));
            mx1 = fmaxf(mx1, __shfl_xor_sync(0xffffffffu, mx1, 2));
            const float a0 = __expf(m0r - mx0), a1 = __expf(m1r - mx1);
            m0r = mx0; m1r = mx1;
            float s0 = 0.f, s1 = 0.f;
#pragma unroll
            for (int nt = 0; nt < 8; nt++) {
                float p00 = __expf(sf[nt][0] - mx0);
                float p01 = __expf(sf[nt][1] - mx0);
                float p10 = __expf(sf[nt][2] - mx1);
                float p11 = __expf(sf[nt][3] - mx1);
                s0 += p00 + p01; s1 += p10 + p11;
                *(float2*)&Pt[(wrow + r) * PAD + nt * 8 + cb * 2] =
                    make_float2(f2tf32f(p00), f2tf32f(p01));
                *(float2*)&Pt[(wrow + 8 + r) * PAD + nt * 8 + cb * 2] =
                    make_float2(f2tf32f(p10), f2tf32f(p11));
            }
            s0 += __shfl_xor_sync(0xffffffffu, s0, 1);
            s0 += __shfl_xor_sync(0xffffffffu, s0, 2);
            s1 += __shfl_xor_sync(0xffffffffu, s1, 1);
            s1 += __shfl_xor_sync(0xffffffffu, s1, 2);
            l0 = l0 * a0 + s0;
            l1 = l1 * a1 + s1;
#pragma unroll
            for (int dt = 0; dt < 8; dt++) {
                of[dt][0] *= a0; of[dt][1] *= a0;
                of[dt][2] *= a1; of[dt][3] *= a1;
            }
            __syncwarp();
            // O += P.V  (A frags via ldmatrix on Pt; V B-frags via ldmatrix)
#pragma unroll
            for (int ks = 0; ks < 8; ks++) {
                uint32_t a[4];
                ldsm_x4(a, pA + ks * 8 * 4);
                uint32_t vf[4][4];
#pragma unroll
                for (int np = 0; np < 4; np++)
                    ldsm_x4(vf[np], vBufA + (np * 16 * PAD + ks * 8) * 4);
#pragma unroll
                for (int dt = 0; dt < 8; dt++)
                    mma_tf32(of[dt], a, &vf[dt >> 1][(dt & 1) * 2]);
            }
        }
    }

    // epilogue: write ctx tf32-rounded (final GEMM reads it raw)
    const float i0 = 1.f / l0, i1 = 1.f / l1;
    float* C0 = g_C + ((size_t)b * SQ + q0 + wrow + r) * DM + h * HDIM;
    float* C1 = C0 + 8 * DM;
#pragma unroll
    for (int dt = 0; dt < 8; dt++) {
        const int col = dt * 8 + cb * 2;
        *(float2*)&C0[col] = make_float2(f2tf32f(of[dt][0] * i0), f2tf32f(of[dt][1] * i0));
        *(float2*)&C1[col] = make_float2(f2tf32f(of[dt][2] * i1), f2tf32f(of[dt][3] * i1));
    }
}

// ---------------------------------------------------------------------------
extern "C" void kernel_launch(void* const* d_in, const int* in_sizes, int n_in,
                              void* d_out, int out_size)
{
    (void)in_sizes; (void)n_in; (void)out_size;
    const float* x  = (const float*)d_in[0];
    const float* Wq = (const float*)d_in[1];
    const float* Wk = (const float*)d_in[2];
    const float* Wv = (const float*)d_in[3];
    const float* Wo = (const float*)d_in[4];
    float* out = (float*)d_out;

    const int M = BATCH * SQ;   // 4096

    cudaFuncSetAttribute(gemm_tc32, cudaFuncAttributeMaxDynamicSharedMemorySize, GEMM_SMEM);
    cudaFuncSetAttribute(gqa_attn_tc, cudaFuncAttributeMaxDynamicSharedMemorySize, ATTN_SMEM);

    float* xt; cudaGetSymbolAddress((void**)&xt, g_Xt);
    float* wt; cudaGetSymbolAddress((void**)&wt, g_Wt);

    // Pre-convert x and all weights to tf32 bit patterns (rna) in ONE launch
    cvt_all<<<(N4_TOTAL + 255) / 256, 256>>>(
        (const float4*)x, (const float4*)Wq, (const float4*)Wk,
        (const float4*)Wv, (const float4*)Wo, (float4*)xt, (float4*)wt);

    // Fused Q|K|V = x @ [Wq;Wk;Wv]^T   (V stored transposed)
    gemm_tc32<<<dim3(3072 / 128, M / 128), 256, GEMM_SMEM>>>(0, 0, 4, nullptr, M, DM);
    // Causal GQA attention -> g_C
    gqa_attn_tc<<<dim3(SQ / 128, BATCH * NH), 256, ATTN_SMEM>>>();
    // out = ctx @ Wo^T
    gemm_tc32<<<dim3(DM / 128, M / 128), 256, GEMM_SMEM>>>(1, WO_OFF, 3, out, M, DM);
}

// round 13
// speedup vs baseline: 2.5718x; 1.8426x over previous
#include <cuda_runtime.h>
#include <cuda_fp16.h>
#include <math.h>
#include <stdint.h>

// Problem constants
#define BATCH 2
#define SQ    2048
#define DM    2048     // model dim
#define KVD   512      // G*HD
#define NH    32       // heads
#define NG    8        // kv groups
#define HDIM  64       // head dim

// Scratch (allocation-free rule: __device__ globals), all fp16
__device__ __half g_Qh[(size_t)BATCH * SQ * DM];   // Q, pre-scaled by 0.125
__device__ __half g_Kh[(size_t)BATCH * SQ * KVD];
__device__ __half g_Vh[(size_t)BATCH * SQ * KVD];  // TRANSPOSED: [b][g][d][s]
__device__ __half g_Ch[(size_t)BATCH * SQ * DM];   // ctx
__device__ __half g_Xh[(size_t)BATCH * SQ * DM];   // x
// packed fp16 weights: Wq | Wk | Wv | Wo
#define WQ_OFF 0
#define WK_OFF (2048 * 2048)
#define WV_OFF (WK_OFF + 512 * 2048)
#define WO_OFF (WV_OFF + 512 * 2048)
__device__ __half g_Wh[WO_OFF + 2048 * 2048];

// ---------------------------------------------------------------------------
// helpers
// ---------------------------------------------------------------------------
__device__ __forceinline__ uint32_t smem_u32(const void* p) {
    uint32_t a;
    asm("{ .reg .u64 t; cvta.to.shared.u64 t, %1; cvt.u32.u64 %0, t; }"
        : "=r"(a) : "l"(p));
    return a;
}
__device__ __forceinline__ void cp_async16(uint32_t dst, const void* src) {
    asm volatile("cp.async.cg.shared.global [%0], [%1], 16;" :: "r"(dst), "l"(src));
}
__device__ __forceinline__ void cp_commit() {
    asm volatile("cp.async.commit_group;" ::: "memory");
}
template <int N>
__device__ __forceinline__ void cp_wait() {
    asm volatile("cp.async.wait_group %0;" :: "n"(N) : "memory");
}
__device__ __forceinline__ void mma_f16(float* c, const uint32_t* a, const uint32_t* b) {
    asm volatile(
        "mma.sync.aligned.m16n8k16.row.col.f32.f16.f16.f32 "
        "{%0,%1,%2,%3}, {%4,%5,%6,%7}, {%8,%9}, {%0,%1,%2,%3};"
        : "+f"(c[0]), "+f"(c[1]), "+f"(c[2]), "+f"(c[3])
        : "r"(a[0]), "r"(a[1]), "r"(a[2]), "r"(a[3]), "r"(b[0]), "r"(b[1]));
}
__device__ __forceinline__ void ldsm_x4(uint32_t* r, uint32_t addr) {
    asm volatile("ldmatrix.sync.aligned.m8n8.x4.shared.b16 {%0,%1,%2,%3}, [%4];"
                 : "=r"(r[0]), "=r"(r[1]), "=r"(r[2]), "=r"(r[3]) : "r"(addr));
}

// ---------------------------------------------------------------------------
// Fused one-shot fp32 -> fp16 conversion for x + all four weights.
// ---------------------------------------------------------------------------
#define N4_X ((BATCH * SQ * DM) / 4)     // 2097152
#define N4_Q ((DM * DM) / 4)             // 1048576
#define N4_K ((KVD * DM) / 4)            // 262144
#define N4_TOTAL (N4_X + 2 * N4_Q + 2 * N4_K)

__global__ __launch_bounds__(256) void cvt_all(
    const float4* __restrict__ x,  const float4* __restrict__ wq,
    const float4* __restrict__ wk, const float4* __restrict__ wv,
    const float4* __restrict__ wo, __half2* __restrict__ xh,
    __half2* __restrict__ wh)
{
    int i = blockIdx.x * 256 + threadIdx.x;
    if (i >= N4_TOTAL) return;
    const float4* s;
    __half2* d;
    if (i < N4_X) { s = x + i; d = xh + i * 2; }
    else {
        int j = i - N4_X;
        d = wh + j * 2;
        if (j < N4_Q)                   s = wq + j;
        else if (j < N4_Q + N4_K)       s = wk + (j - N4_Q);
        else if (j < N4_Q + 2 * N4_K)   s = wv + (j - N4_Q - N4_K);
        else                            s = wo + (j - N4_Q - 2 * N4_K);
    }
    float4 v = *s;
    d[0] = __floats2half2_rn(v.x, v.y);
    d[1] = __floats2half2_rn(v.z, v.w);
}

// ---------------------------------------------------------------------------
// FP16 mma.sync GEMM:  C[M,N] = A[M,K] . W[N,K]^T   (fp32 accumulate)
// CTA: 128x128 tile, BK=64 halves, 256 threads (8 warps, 2m x 4n; warp 64x32).
// 3-stage cp.async, ONE __syncthreads per k-tile; prefetch after ks=0 MMAs.
// csel 4 = fused QKV (Q scaled 0.125, V transposed); csel 3 = fp32 out.
// ---------------------------------------------------------------------------
#define HSTRIDE 72                            // halves per smem row (64 + pad)
#define STG_B (2 * 128 * HSTRIDE * 2)         // bytes per stage (A+B) = 36864
#define GEMM_SMEM (3 * STG_B)                 // 110592 bytes

__global__ __launch_bounds__(256, 2) void gemm_f16(
    int asel, int woff, int csel, float* __restrict__ Cext, int M, int K)
{
    extern __shared__ char smc[];
    const uint32_t sb = smem_u32(smc);
    const __half* A = asel ? g_Ch : g_Xh;
    const __half* W = g_Wh + woff;

    const int tid = threadIdx.x;
    const int wid = tid >> 5;
    const int lane = tid & 31;
    const int m0 = blockIdx.y * 128;
    const int n0 = blockIdx.x * 128;
    const int wm0 = (wid >> 2) * 64;
    const int wn0 = (wid & 3) * 32;

    // output routing
    __half* Ch = nullptr;
    int ldc = DM, cbase = n0;
    bool vtrans = false;
    float oscale = 1.f;
    if (csel == 4) {
        if (n0 < 2048)      { Ch = g_Qh; ldc = DM;  cbase = n0; oscale = 0.125f; }
        else if (n0 < 2560) { Ch = g_Kh; ldc = KVD; cbase = n0 - 2048; }
        else                { vtrans = true; cbase = n0 - 2560; }
    }

    // ldmatrix lane roles
    const int lt = lane & 7;
    const int tt = lane >> 3;
    const int arow = wm0 + lt + (tt & 1) * 8;
    const int acol = (tt >> 1) * 8;          // halves
    const int brow = wn0 + lt + (tt >> 1) * 8;
    const int bcol = (tt & 1) * 8;           // halves

    float c[4][4][4];
#pragma unroll
    for (int mt = 0; mt < 4; mt++)
#pragma unroll
        for (int nt = 0; nt < 4; nt++)
#pragma unroll
            for (int i = 0; i < 4; i++) c[mt][nt][i] = 0.f;

    const int nk = K / 64;

    auto issue = [&](int kt, int buf) {
        const uint32_t abase = sb + buf * STG_B;
        const uint32_t bbase = abase + 128 * HSTRIDE * 2;
        const int k0 = kt * 64;
#pragma unroll
        for (int i = 0; i < 4; i++) {
            int idx = tid + i * 256;           // 0..1023
            int row = idx >> 3;
            int ch = idx & 7;                  // 16B chunk = 8 halves
            cp_async16(abase + (row * HSTRIDE + ch * 8) * 2,
                       &A[(size_t)(m0 + row) * K + k0 + ch * 8]);
            cp_async16(bbase + (row * HSTRIDE + ch * 8) * 2,
                       &W[(size_t)(n0 + row) * K + k0 + ch * 8]);
        }
        cp_commit();
    };

    issue(0, 0);
    issue(1, 1);

    int buf = 0, wbuf = 2;
    for (int kt = 0; kt < nk; kt++) {
        cp_wait<1>();
        __syncthreads();

        const uint32_t stg = sb + buf * STG_B;
        const uint32_t a_base = stg + (arow * HSTRIDE + acol) * 2;
        const uint32_t b_base = stg + 128 * HSTRIDE * 2 + (brow * HSTRIDE + bcol) * 2;

#pragma unroll
        for (int ks = 0; ks < 4; ks++) {       // 4 x k16 = 64
            uint32_t a[4][4], b[2][4];
#pragma unroll
            for (int mt = 0; mt < 4; mt++)
                ldsm_x4(a[mt], a_base + (mt * 16 * HSTRIDE + ks * 16) * 2);
#pragma unroll
            for (int np = 0; np < 2; np++)
                ldsm_x4(b[np], b_base + (np * 16 * HSTRIDE + ks * 16) * 2);
#pragma unroll
            for (int mt = 0; mt < 4; mt++)
#pragma unroll
                for (int nt = 0; nt < 4; nt++)
                    mma_f16(c[mt][nt], a[mt], &b[nt >> 1][(nt & 1) * 2]);

            if (ks == 0) {
                if (kt + 2 < nk) issue(kt + 2, wbuf);
                else cp_commit();
            }
        }
        buf = (buf == 2) ? 0 : buf + 1;
        wbuf = (wbuf == 2) ? 0 : wbuf + 1;
    }

#pragma unroll
    for (int mt = 0; mt < 4; mt++) {
        const int r0 = m0 + wm0 + mt * 16 + (lane >> 2);
#pragma unroll
        for (int nt = 0; nt < 4; nt++) {
            const int col = cbase + wn0 + nt * 8 + (lane & 3) * 2;
            float v0 = c[mt][nt][0], v1 = c[mt][nt][1];
            float v2 = c[mt][nt][2], v3 = c[mt][nt][3];
            if (csel == 3) {
                *(float2*)&Cext[(size_t)r0 * DM + col] = make_float2(v0, v1);
                *(float2*)&Cext[(size_t)(r0 + 8) * DM + col] = make_float2(v2, v3);
            } else if (vtrans) {
                // V^T: g_Vh[((b*NG+g)*HDIM + d) * SQ + s]
                const int bb = r0 >> 11, s = r0 & 2047;
                const int gg = col >> 6, d = col & 63;
                __half* base = g_Vh + ((size_t)(bb * NG + gg) * HDIM + d) * SQ + s;
                base[0]      = __float2half_rn(v0);
                base[SQ]     = __float2half_rn(v1);
                base[8]      = __float2half_rn(v2);
                base[SQ + 8] = __float2half_rn(v3);
            } else {
                *(__half2*)&Ch[(size_t)r0 * ldc + col] =
                    __floats2half2_rn(v0 * oscale, v1 * oscale);
                *(__half2*)&Ch[(size_t)(r0 + 8) * ldc + col] =
                    __floats2half2_rn(v2 * oscale, v3 * oscale);
            }
        }
    }
}

// ---------------------------------------------------------------------------
// FP16 tensor-core causal GQA flash attention (fp32 softmax/accum).
// CTA: (qt, b*32+h); 256 threads = 8 warps; BQ=128 (16 q-rows/warp), BKV=64.
// Q (pre-scaled), K, V^T all fp16 via cp.async; all frags via ldmatrix.
// ONE __syncthreads per kv-tile; prefetch after QK MMA phase.
// ---------------------------------------------------------------------------
#define TPAD  72                              // halves per row
#define KBUF_B (64 * TPAD * 2)                // 9216 bytes per K or V buffer
#define ATTN_SMEM (4 * KBUF_B + 128 * TPAD * 2)   // 55296 bytes

__global__ __launch_bounds__(256, 2) void gqa_attn_tc()
{
    extern __shared__ char smc[];
    const uint32_t sb = smem_u32(smc);
    const uint32_t sbK = sb;
    const uint32_t sbV = sb + 2 * KBUF_B;
    const uint32_t sbP = sb + 4 * KBUF_B;
    __half* Pt = (__half*)(smc + 4 * KBUF_B);   // [128][TPAD]

    const int tid = threadIdx.x;
    const int w = tid >> 5;
    const int lane = tid & 31;
    const int r = lane >> 2;
    const int cb = lane & 3;
    const int qt = (int)gridDim.x - 1 - (int)blockIdx.x;   // heavy tiles first
    const int bh = blockIdx.y;
    const int b = bh >> 5, h = bh & 31, g = h >> 2;
    const int q0 = qt * 128;
    const int wrow = w * 16;

    // ldmatrix lane roles (A-pattern for Q/P, B-pattern for K/V)
    const int lt = lane & 7;
    const int tt = lane >> 3;
    const int parow = wrow + lt + (tt & 1) * 8;
    const int pacol = (tt >> 1) * 8;          // halves
    const int nbrow = lt + (tt >> 1) * 8;     // B-frag n row (kv for K, d for V)
    const int nbcol = (tt & 1) * 8;           // B-frag k col (halves)

    const __half* Qb = g_Qh + (size_t)b * SQ * DM + h * HDIM;
    const __half* Kb = g_Kh + (size_t)b * SQ * KVD + g * HDIM;
    const __half* Vb = g_Vh + (size_t)(b * NG + g) * HDIM * SQ;   // [d][s]

    // Stage Q tile into Pt via cp.async (already scaled by 0.125)
#pragma unroll
    for (int i = 0; i < 4; i++) {
        int idx = tid + i * 256;               // 128 rows x 8 chunks
        int row = idx >> 3, ch = idx & 7;
        cp_async16(sbP + (row * TPAD + ch * 8) * 2,
                   &Qb[(size_t)(q0 + row) * DM + ch * 8]);
    }
    cp_commit();
    cp_wait<0>();
    __syncthreads();

    const uint32_t pA = sbP + (parow * TPAD + pacol) * 2;
    uint32_t qf[4][4];
#pragma unroll
    for (int ks = 0; ks < 4; ks++)
        ldsm_x4(qf[ks], pA + ks * 16 * 2);
    __syncthreads();

    float of[8][4];
#pragma unroll
    for (int dt = 0; dt < 8; dt++)
#pragma unroll
        for (int i = 0; i < 4; i++) of[dt][i] = 0.f;
    float m0r = -1e30f, m1r = -1e30f, l0 = 0.f, l1 = 0.f;

    const int nkt = qt * 2 + 2;

    auto issue_tile = [&](int kt) {
        const int buf = kt & 1;
        const uint32_t kbuf = sbK + buf * KBUF_B;
        const uint32_t vbuf = sbV + buf * KBUF_B;
        const int k0 = kt * 64;
#pragma unroll
        for (int i = 0; i < 2; i++) {
            int idx = tid + i * 256;           // 64 rows x 8 chunks
            int row = idx >> 3, ch = idx & 7;
            cp_async16(kbuf + (row * TPAD + ch * 8) * 2,
                       &Kb[(size_t)(k0 + row) * KVD + ch * 8]);
            cp_async16(vbuf + (row * TPAD + ch * 8) * 2,
                       &Vb[(size_t)row * SQ + k0 + ch * 8]);
        }
        cp_commit();
    };

    issue_tile(0);

    for (int kt = 0; kt < nkt; kt++) {
        cp_wait<0>();
        __syncthreads();

        const uint32_t kBufA = sbK + (kt & 1) * KBUF_B + (nbrow * TPAD + nbcol) * 2;
        const uint32_t vBufA = sbV + (kt & 1) * KBUF_B + (nbrow * TPAD + nbcol) * 2;
        const int k0 = kt * 64;

        const bool active = (k0 <= q0 + wrow + 15);
        float sf[8][4];
        if (active) {
#pragma unroll
            for (int nt = 0; nt < 8; nt++)
#pragma unroll
                for (int i = 0; i < 4; i++) sf[nt][i] = 0.f;
#pragma unroll
            for (int ks = 0; ks < 4; ks++) {   // k16 over d=64
                uint32_t bf[4][4];
#pragma unroll
                for (int np = 0; np < 4; np++)
                    ldsm_x4(bf[np], kBufA + (np * 16 * TPAD + ks * 16) * 2);
#pragma unroll
                for (int nt = 0; nt < 8; nt++)
                    mma_f16(sf[nt], qf[ks], &bf[nt >> 1][(nt & 1) * 2]);
            }
        }

        if (kt + 1 < nkt) issue_tile(kt + 1);

        if (active) {
            if (k0 + 63 > q0 + wrow) {
                const int qr0 = q0 + wrow + r;
                const int qr1 = qr0 + 8;
#pragma unroll
                for (int nt = 0; nt < 8; nt++) {
                    const int kvc = k0 + nt * 8 + cb * 2;
                    if (kvc > qr0)     sf[nt][0] = -1e30f;
                    if (kvc + 1 > qr0) sf[nt][1] = -1e30f;
                    if (kvc > qr1)     sf[nt][2] = -1e30f;
                    if (kvc + 1 > qr1) sf[nt][3] = -1e30f;
                }
            }
            float mx0 = m0r, mx1 = m1r;
#pragma unroll
            for (int nt = 0; nt < 8; nt++) {
                mx0 = fmaxf(mx0, fmaxf(sf[nt][0], sf[nt][1]));
                mx1 = fmaxf(mx1, fmaxf(sf[nt][2], sf[nt][3]));
            }
            mx0 = fmaxf(mx0, __shfl_xor_sync(0xffffffffu, mx0, 1));
            mx0 = fmaxf(mx0, __shfl_xor_sync(0xffffffffu, mx0, 2));
            mx1 = fmaxf(mx1, __shfl_xor_sync(0xffffffffu, mx1, 1));
            mx1 = fmaxf(mx1, __shfl_xor_sync(0xffffffffu, mx1, 2));
            const float a0 = __expf(m0r - mx0), a1 = __expf(m1r - mx1);
            m0r = mx0; m1r = mx1;
            float s0 = 0.f, s1 = 0.f;
#pragma unroll
            for (int nt = 0; nt < 8; nt++) {
                float p00 = __expf(sf[nt][0] - mx0);
                float p01 = __expf(sf[nt][1] - mx0);
                float p10 = __expf(sf[nt][2] - mx1);
                float p11 = __expf(sf[nt][3] - mx1);
                s0 += p00 + p01; s1 += p10 + p11;
                *(__half2*)&Pt[(wrow + r) * TPAD + nt * 8 + cb * 2] =
                    __floats2half2_rn(p00, p01);
                *(__half2*)&Pt[(wrow + 8 + r) * TPAD + nt * 8 + cb * 2] =
                    __floats2half2_rn(p10, p11);
            }
            s0 += __shfl_xor_sync(0xffffffffu, s0, 1);
            s0 += __shfl_xor_sync(0xffffffffu, s0, 2);
            s1 += __shfl_xor_sync(0xffffffffu, s1, 1);
            s1 += __shfl_xor_sync(0xffffffffu, s1, 2);
            l0 = l0 * a0 + s0;
            l1 = l1 * a1 + s1;
#pragma unroll
            for (int dt = 0; dt < 8; dt++) {
                of[dt][0] *= a0; of[dt][1] *= a0;
                of[dt][2] *= a1; of[dt][3] *= a1;
            }
            __syncwarp();
            // O += P.V  (A = P frags, B = V^T frags, both ldmatrix)
#pragma unroll
            for (int ks = 0; ks < 4; ks++) {   // k16 over kv=64
                uint32_t a[4];
                ldsm_x4(a, pA + ks * 16 * 2);
                uint32_t vf[4][4];
#pragma unroll
                for (int np = 0; np < 4; np++)
                    ldsm_x4(vf[np], vBufA + (np * 16 * TPAD + ks * 16) * 2);
#pragma unroll
                for (int dt = 0; dt < 8; dt++)
                    mma_f16(of[dt], a, &vf[dt >> 1][(dt & 1) * 2]);
            }
        }
    }

    // epilogue: ctx (fp16) for the final GEMM
    const float i0 = 1.f / l0, i1 = 1.f / l1;
    __half* C0 = g_Ch + ((size_t)b * SQ + q0 + wrow + r) * DM + h * HDIM;
    __half* C1 = C0 + 8 * DM;
#pragma unroll
    for (int dt = 0; dt < 8; dt++) {
        const int col = dt * 8 + cb * 2;
        *(__half2*)&C0[col] = __floats2half2_rn(of[dt][0] * i0, of[dt][1] * i0);
        *(__half2*)&C1[col] = __floats2half2_rn(of[dt][2] * i1, of[dt][3] * i1);
    }
}

// ---------------------------------------------------------------------------
extern "C" void kernel_launch(void* const* d_in, const int* in_sizes, int n_in,
                              void* d_out, int out_size)
{
    (void)in_sizes; (void)n_in; (void)out_size;
    const float* x  = (const float*)d_in[0];
    const float* Wq = (const float*)d_in[1];
    const float* Wk = (const float*)d_in[2];
    const float* Wv = (const float*)d_in[3];
    const float* Wo = (const float*)d_in[4];
    float* out = (float*)d_out;

    const int M = BATCH * SQ;   // 4096

    cudaFuncSetAttribute(gemm_f16, cudaFuncAttributeMaxDynamicSharedMemorySize, GEMM_SMEM);
    cudaFuncSetAttribute(gqa_attn_tc, cudaFuncAttributeMaxDynamicSharedMemorySize, ATTN_SMEM);

    __half* xh; cudaGetSymbolAddress((void**)&xh, g_Xh);
    __half* wh; cudaGetSymbolAddress((void**)&wh, g_Wh);

    // Pre-convert x and all weights to fp16 in ONE launch
    cvt_all<<<(N4_TOTAL + 255) / 256, 256>>>(
        (const float4*)x, (const float4*)Wq, (const float4*)Wk,
        (const float4*)Wv, (const float4*)Wo, (__half2*)xh, (__half2*)wh);

    // Fused Q|K|V = x @ [Wq;Wk;Wv]^T  (Q scaled 0.125, V transposed)
    gemm_f16<<<dim3(3072 / 128, M / 128), 256, GEMM_SMEM>>>(0, 0, 4, nullptr, M, DM);
    // Causal GQA attention -> g_Ch
    gqa_attn_tc<<<dim3(SQ / 128, BATCH * NH), 256, ATTN_SMEM>>>();
    // out = ctx @ Wo^T  (fp32 output)
    gemm_f16<<<dim3(DM / 128, M / 128), 256, GEMM_SMEM>>>(1, WO_OFF, 3, out, M, DM);
}

// round 14
// speedup vs baseline: 2.6214x; 1.0193x over previous
#include <cuda_runtime.h>
#include <cuda_fp16.h>
#include <math.h>
#include <stdint.h>

// Problem constants
#define BATCH 2
#define SQ    2048
#define DM    2048     // model dim
#define KVD   512      // G*HD
#define NH    32       // heads
#define NG    8        // kv groups
#define HDIM  64       // head dim

// Scratch (allocation-free rule: __device__ globals), all fp16
__device__ __half g_Qh[(size_t)BATCH * SQ * DM];   // Q, pre-scaled by 0.125
__device__ __half g_Kh[(size_t)BATCH * SQ * KVD];
__device__ __half g_Vh[(size_t)BATCH * SQ * KVD];  // TRANSPOSED: [b][g][d][s]
__device__ __half g_Ch[(size_t)BATCH * SQ * DM];   // ctx
__device__ __half g_Xh[(size_t)BATCH * SQ * DM];   // x
// packed fp16 weights: Wq | Wk | Wv | Wo
#define WQ_OFF 0
#define WK_OFF (2048 * 2048)
#define WV_OFF (WK_OFF + 512 * 2048)
#define WO_OFF (WV_OFF + 512 * 2048)
__device__ __half g_Wh[WO_OFF + 2048 * 2048];

// ---------------------------------------------------------------------------
// helpers
// ---------------------------------------------------------------------------
__device__ __forceinline__ uint32_t smem_u32(const void* p) {
    uint32_t a;
    asm("{ .reg .u64 t; cvta.to.shared.u64 t, %1; cvt.u32.u64 %0, t; }"
        : "=r"(a) : "l"(p));
    return a;
}
__device__ __forceinline__ void cp_async16(uint32_t dst, const void* src) {
    asm volatile("cp.async.cg.shared.global [%0], [%1], 16;" :: "r"(dst), "l"(src));
}
__device__ __forceinline__ void cp_commit() {
    asm volatile("cp.async.commit_group;" ::: "memory");
}
template <int N>
__device__ __forceinline__ void cp_wait() {
    asm volatile("cp.async.wait_group %0;" :: "n"(N) : "memory");
}
__device__ __forceinline__ void mma_f16(float* c, const uint32_t* a, const uint32_t* b) {
    asm volatile(
        "mma.sync.aligned.m16n8k16.row.col.f32.f16.f16.f32 "
        "{%0,%1,%2,%3}, {%4,%5,%6,%7}, {%8,%9}, {%0,%1,%2,%3};"
        : "+f"(c[0]), "+f"(c[1]), "+f"(c[2]), "+f"(c[3])
        : "r"(a[0]), "r"(a[1]), "r"(a[2]), "r"(a[3]), "r"(b[0]), "r"(b[1]));
}
__device__ __forceinline__ void ldsm_x4(uint32_t* r, uint32_t addr) {
    asm volatile("ldmatrix.sync.aligned.m8n8.x4.shared.b16 {%0,%1,%2,%3}, [%4];"
                 : "=r"(r[0]), "=r"(r[1]), "=r"(r[2]), "=r"(r[3]) : "r"(addr));
}
__device__ __forceinline__ uint32_t packh2(float lo, float hi) {
    __half2 h = __floats2half2_rn(lo, hi);
    return *(uint32_t*)&h;
}

// ---------------------------------------------------------------------------
// Fused one-shot fp32 -> fp16 conversion for x + all four weights.
// ---------------------------------------------------------------------------
#define N4_X ((BATCH * SQ * DM) / 4)     // 2097152
#define N4_Q ((DM * DM) / 4)             // 1048576
#define N4_K ((KVD * DM) / 4)            // 262144
#define N4_TOTAL (N4_X + 2 * N4_Q + 2 * N4_K)

__global__ __launch_bounds__(256) void cvt_all(
    const float4* __restrict__ x,  const float4* __restrict__ wq,
    const float4* __restrict__ wk, const float4* __restrict__ wv,
    const float4* __restrict__ wo, __half2* __restrict__ xh,
    __half2* __restrict__ wh)
{
    int i = blockIdx.x * 256 + threadIdx.x;
    if (i >= N4_TOTAL) return;
    const float4* s;
    __half2* d;
    if (i < N4_X) { s = x + i; d = xh + i * 2; }
    else {
        int j = i - N4_X;
        d = wh + j * 2;
        if (j < N4_Q)                   s = wq + j;
        else if (j < N4_Q + N4_K)       s = wk + (j - N4_Q);
        else if (j < N4_Q + 2 * N4_K)   s = wv + (j - N4_Q - N4_K);
        else                            s = wo + (j - N4_Q - 2 * N4_K);
    }
    float4 v = *s;
    d[0] = __floats2half2_rn(v.x, v.y);
    d[1] = __floats2half2_rn(v.z, v.w);
}

// ---------------------------------------------------------------------------
// FP16 mma.sync GEMM:  C[M,N] = A[M,K] . W[N,K]^T   (fp32 accumulate)
// CTA: 128x128 tile, BK=64 halves, 256 threads (8 warps, 2m x 4n; warp 64x32).
// 3-stage cp.async, ONE __syncthreads per k-tile; prefetch after ks=0 MMAs.
// csel 4 = fused QKV (Q scaled 0.125, V transposed); csel 3 = fp32 out.
// ---------------------------------------------------------------------------
#define HSTRIDE 72                            // halves per smem row (64 + pad)
#define STG_B (2 * 128 * HSTRIDE * 2)         // bytes per stage (A+B) = 36864
#define GEMM_SMEM (3 * STG_B)                 // 110592 bytes

__global__ __launch_bounds__(256, 2) void gemm_f16(
    int asel, int woff, int csel, float* __restrict__ Cext, int M, int K)
{
    extern __shared__ char smc[];
    const uint32_t sb = smem_u32(smc);
    const __half* A = asel ? g_Ch : g_Xh;
    const __half* W = g_Wh + woff;

    const int tid = threadIdx.x;
    const int wid = tid >> 5;
    const int lane = tid & 31;
    const int m0 = blockIdx.y * 128;
    const int n0 = blockIdx.x * 128;
    const int wm0 = (wid >> 2) * 64;
    const int wn0 = (wid & 3) * 32;

    // output routing
    __half* Ch = nullptr;
    int ldc = DM, cbase = n0;
    bool vtrans = false;
    float oscale = 1.f;
    if (csel == 4) {
        if (n0 < 2048)      { Ch = g_Qh; ldc = DM;  cbase = n0; oscale = 0.125f; }
        else if (n0 < 2560) { Ch = g_Kh; ldc = KVD; cbase = n0 - 2048; }
        else                { vtrans = true; cbase = n0 - 2560; }
    }

    // ldmatrix lane roles
    const int lt = lane & 7;
    const int tt = lane >> 3;
    const int arow = wm0 + lt + (tt & 1) * 8;
    const int acol = (tt >> 1) * 8;          // halves
    const int brow = wn0 + lt + (tt >> 1) * 8;
    const int bcol = (tt & 1) * 8;           // halves

    float c[4][4][4];
#pragma unroll
    for (int mt = 0; mt < 4; mt++)
#pragma unroll
        for (int nt = 0; nt < 4; nt++)
#pragma unroll
            for (int i = 0; i < 4; i++) c[mt][nt][i] = 0.f;

    const int nk = K / 64;

    auto issue = [&](int kt, int buf) {
        const uint32_t abase = sb + buf * STG_B;
        const uint32_t bbase = abase + 128 * HSTRIDE * 2;
        const int k0 = kt * 64;
#pragma unroll
        for (int i = 0; i < 4; i++) {
            int idx = tid + i * 256;           // 0..1023
            int row = idx >> 3;
            int ch = idx & 7;                  // 16B chunk = 8 halves
            cp_async16(abase + (row * HSTRIDE + ch * 8) * 2,
                       &A[(size_t)(m0 + row) * K + k0 + ch * 8]);
            cp_async16(bbase + (row * HSTRIDE + ch * 8) * 2,
                       &W[(size_t)(n0 + row) * K + k0 + ch * 8]);
        }
        cp_commit();
    };

    issue(0, 0);
    issue(1, 1);

    int buf = 0, wbuf = 2;
    for (int kt = 0; kt < nk; kt++) {
        cp_wait<1>();
        __syncthreads();

        const uint32_t stg = sb + buf * STG_B;
        const uint32_t a_base = stg + (arow * HSTRIDE + acol) * 2;
        const uint32_t b_base = stg + 128 * HSTRIDE * 2 + (brow * HSTRIDE + bcol) * 2;

#pragma unroll
        for (int ks = 0; ks < 4; ks++) {       // 4 x k16 = 64
            uint32_t a[4][4], b[2][4];
#pragma unroll
            for (int mt = 0; mt < 4; mt++)
                ldsm_x4(a[mt], a_base + (mt * 16 * HSTRIDE + ks * 16) * 2);
#pragma unroll
            for (int np = 0; np < 2; np++)
                ldsm_x4(b[np], b_base + (np * 16 * HSTRIDE + ks * 16) * 2);
#pragma unroll
            for (int mt = 0; mt < 4; mt++)
#pragma unroll
                for (int nt = 0; nt < 4; nt++)
                    mma_f16(c[mt][nt], a[mt], &b[nt >> 1][(nt & 1) * 2]);

            if (ks == 0) {
                if (kt + 2 < nk) issue(kt + 2, wbuf);
                else cp_commit();
            }
        }
        buf = (buf == 2) ? 0 : buf + 1;
        wbuf = (wbuf == 2) ? 0 : wbuf + 1;
    }

#pragma unroll
    for (int mt = 0; mt < 4; mt++) {
        const int r0 = m0 + wm0 + mt * 16 + (lane >> 2);
#pragma unroll
        for (int nt = 0; nt < 4; nt++) {
            const int col = cbase + wn0 + nt * 8 + (lane & 3) * 2;
            float v0 = c[mt][nt][0], v1 = c[mt][nt][1];
            float v2 = c[mt][nt][2], v3 = c[mt][nt][3];
            if (csel == 3) {
                *(float2*)&Cext[(size_t)r0 * DM + col] = make_float2(v0, v1);
                *(float2*)&Cext[(size_t)(r0 + 8) * DM + col] = make_float2(v2, v3);
            } else if (vtrans) {
                // V^T: g_Vh[((b*NG+g)*HDIM + d) * SQ + s]
                const int bb = r0 >> 11, s = r0 & 2047;
                const int gg = col >> 6, d = col & 63;
                __half* base = g_Vh + ((size_t)(bb * NG + gg) * HDIM + d) * SQ + s;
                base[0]      = __float2half_rn(v0);
                base[SQ]     = __float2half_rn(v1);
                base[8]      = __float2half_rn(v2);
                base[SQ + 8] = __float2half_rn(v3);
            } else {
                *(__half2*)&Ch[(size_t)r0 * ldc + col] =
                    __floats2half2_rn(v0 * oscale, v1 * oscale);
                *(__half2*)&Ch[(size_t)(r0 + 8) * ldc + col] =
                    __floats2half2_rn(v2 * oscale, v3 * oscale);
            }
        }
    }
}

// ---------------------------------------------------------------------------
// FP16 tensor-core causal GQA flash attention (fp32 softmax/accum).
// CTA: (qt, b*32+h); 256 threads = 8 warps; BQ=128 (16 q-rows/warp), BKV=64.
// Register-direct P: the S C-fragment converts in-register to the PV
// A-fragment (half2 packs, n-tile pairs) — no smem round-trip.
// ONE __syncthreads per kv-tile; prefetch after QK MMA phase.
// ---------------------------------------------------------------------------
#define TPAD  72                              // halves per row
#define KBUF_B (64 * TPAD * 2)                // 9216 bytes per K or V buffer
#define ATTN_SMEM (4 * KBUF_B + 128 * TPAD * 2)   // 55296 bytes

__global__ __launch_bounds__(256, 2) void gqa_attn_tc()
{
    extern __shared__ char smc[];
    const uint32_t sb = smem_u32(smc);
    const uint32_t sbK = sb;
    const uint32_t sbV = sb + 2 * KBUF_B;
    const uint32_t sbP = sb + 4 * KBUF_B;     // Q staging only

    const int tid = threadIdx.x;
    const int w = tid >> 5;
    const int lane = tid & 31;
    const int r = lane >> 2;
    const int cb = lane & 3;
    const int qt = (int)gridDim.x - 1 - (int)blockIdx.x;   // heavy tiles first
    const int bh = blockIdx.y;
    const int b = bh >> 5, h = bh & 31, g = h >> 2;
    const int q0 = qt * 128;
    const int wrow = w * 16;

    // ldmatrix lane roles (A-pattern for Q, B-pattern for K/V)
    const int lt = lane & 7;
    const int tt = lane >> 3;
    const int parow = wrow + lt + (tt & 1) * 8;
    const int pacol = (tt >> 1) * 8;          // halves
    const int nbrow = lt + (tt >> 1) * 8;     // B-frag n row (kv for K, d for V)
    const int nbcol = (tt & 1) * 8;           // B-frag k col (halves)

    const __half* Qb = g_Qh + (size_t)b * SQ * DM + h * HDIM;
    const __half* Kb = g_Kh + (size_t)b * SQ * KVD + g * HDIM;
    const __half* Vb = g_Vh + (size_t)(b * NG + g) * HDIM * SQ;   // [d][s]

    // Stage Q tile via cp.async (already scaled by 0.125)
#pragma unroll
    for (int i = 0; i < 4; i++) {
        int idx = tid + i * 256;               // 128 rows x 8 chunks
        int row = idx >> 3, ch = idx & 7;
        cp_async16(sbP + (row * TPAD + ch * 8) * 2,
                   &Qb[(size_t)(q0 + row) * DM + ch * 8]);
    }
    cp_commit();
    cp_wait<0>();
    __syncthreads();

    const uint32_t pA = sbP + (parow * TPAD + pacol) * 2;
    uint32_t qf[4][4];
#pragma unroll
    for (int ks = 0; ks < 4; ks++)
        ldsm_x4(qf[ks], pA + ks * 16 * 2);
    __syncthreads();

    float of[8][4];
#pragma unroll
    for (int dt = 0; dt < 8; dt++)
#pragma unroll
        for (int i = 0; i < 4; i++) of[dt][i] = 0.f;
    float m0r = -1e30f, m1r = -1e30f, l0 = 0.f, l1 = 0.f;

    const int nkt = qt * 2 + 2;

    auto issue_tile = [&](int kt) {
        const int buf = kt & 1;
        const uint32_t kbuf = sbK + buf * KBUF_B;
        const uint32_t vbuf = sbV + buf * KBUF_B;
        const int k0 = kt * 64;
#pragma unroll
        for (int i = 0; i < 2; i++) {
            int idx = tid + i * 256;           // 64 rows x 8 chunks
            int row = idx >> 3, ch = idx & 7;
            cp_async16(kbuf + (row * TPAD + ch * 8) * 2,
                       &Kb[(size_t)(k0 + row) * KVD + ch * 8]);
            cp_async16(vbuf + (row * TPAD + ch * 8) * 2,
                       &Vb[(size_t)row * SQ + k0 + ch * 8]);
        }
        cp_commit();
    };

    issue_tile(0);

    for (int kt = 0; kt < nkt; kt++) {
        cp_wait<0>();
        __syncthreads();

        const uint32_t kBufA = sbK + (kt & 1) * KBUF_B + (nbrow * TPAD + nbcol) * 2;
        const uint32_t vBufA = sbV + (kt & 1) * KBUF_B + (nbrow * TPAD + nbcol) * 2;
        const int k0 = kt * 64;

        const bool active = (k0 <= q0 + wrow + 15);
        float sf[8][4];
        if (active) {
#pragma unroll
            for (int nt = 0; nt < 8; nt++)
#pragma unroll
                for (int i = 0; i < 4; i++) sf[nt][i] = 0.f;
#pragma unroll
            for (int ks = 0; ks < 4; ks++) {   // k16 over d=64
                uint32_t bf[4][4];
#pragma unroll
                for (int np = 0; np < 4; np++)
                    ldsm_x4(bf[np], kBufA + (np * 16 * TPAD + ks * 16) * 2);
#pragma unroll
                for (int nt = 0; nt < 8; nt++)
                    mma_f16(sf[nt], qf[ks], &bf[nt >> 1][(nt & 1) * 2]);
            }
        }

        if (kt + 1 < nkt) issue_tile(kt + 1);

        if (active) {
            if (k0 + 63 > q0 + wrow) {
                const int qr0 = q0 + wrow + r;
                const int qr1 = qr0 + 8;
#pragma unroll
                for (int nt = 0; nt < 8; nt++) {
                    const int kvc = k0 + nt * 8 + cb * 2;
                    if (kvc > qr0)     sf[nt][0] = -1e30f;
                    if (kvc + 1 > qr0) sf[nt][1] = -1e30f;
                    if (kvc > qr1)     sf[nt][2] = -1e30f;
                    if (kvc + 1 > qr1) sf[nt][3] = -1e30f;
                }
            }
            float mx0 = m0r, mx1 = m1r;
#pragma unroll
            for (int nt = 0; nt < 8; nt++) {
                mx0 = fmaxf(mx0, fmaxf(sf[nt][0], sf[nt][1]));
                mx1 = fmaxf(mx1, fmaxf(sf[nt][2], sf[nt][3]));
            }
            mx0 = fmaxf(mx0, __shfl_xor_sync(0xffffffffu, mx0, 1));
            mx0 = fmaxf(mx0, __shfl_xor_sync(0xffffffffu, mx0, 2));
            mx1 = fmaxf(mx1, __shfl_xor_sync(0xffffffffu, mx1, 1));
            mx1 = fmaxf(mx1, __shfl_xor_sync(0xffffffffu, mx1, 2));
            const float a0 = __expf(m0r - mx0), a1 = __expf(m1r - mx1);
            m0r = mx0; m1r = mx1;
            float s0 = 0.f, s1 = 0.f;
            // exp + in-register C->A fragment conversion (half2 packs)
            uint32_t pf[4][4];
#pragma unroll
            for (int nt = 0; nt < 8; nt++) {
                float p00 = __expf(sf[nt][0] - mx0);
                float p01 = __expf(sf[nt][1] - mx0);
                float p10 = __expf(sf[nt][2] - mx1);
                float p11 = __expf(sf[nt][3] - mx1);
                s0 += p00 + p01; s1 += p10 + p11;
                pf[nt >> 1][(nt & 1) * 2 + 0] = packh2(p00, p01);
                pf[nt >> 1][(nt & 1) * 2 + 1] = packh2(p10, p11);
            }
            s0 += __shfl_xor_sync(0xffffffffu, s0, 1);
            s0 += __shfl_xor_sync(0xffffffffu, s0, 2);
            s1 += __shfl_xor_sync(0xffffffffu, s1, 1);
            s1 += __shfl_xor_sync(0xffffffffu, s1, 2);
            l0 = l0 * a0 + s0;
            l1 = l1 * a1 + s1;
#pragma unroll
            for (int dt = 0; dt < 8; dt++) {
                of[dt][0] *= a0; of[dt][1] *= a0;
                of[dt][2] *= a1; of[dt][3] *= a1;
            }
            // O += P.V  (A = pf registers, B = V^T frags via ldmatrix)
#pragma unroll
            for (int ks = 0; ks < 4; ks++) {   // k16 over kv=64
                uint32_t vf[4][4];
#pragma unroll
                for (int np = 0; np < 4; np++)
                    ldsm_x4(vf[np], vBufA + (np * 16 * TPAD + ks * 16) * 2);
#pragma unroll
                for (int dt = 0; dt < 8; dt++)
                    mma_f16(of[dt], pf[ks], &vf[dt >> 1][(dt & 1) * 2]);
            }
        }
    }

    // epilogue: ctx (fp16) for the final GEMM
    const float i0 = 1.f / l0, i1 = 1.f / l1;
    __half* C0 = g_Ch + ((size_t)b * SQ + q0 + wrow + r) * DM + h * HDIM;
    __half* C1 = C0 + 8 * DM;
#pragma unroll
    for (int dt = 0; dt < 8; dt++) {
        const int col = dt * 8 + cb * 2;
        *(__half2*)&C0[col] = __floats2half2_rn(of[dt][0] * i0, of[dt][1] * i0);
        *(__half2*)&C1[col] = __floats2half2_rn(of[dt][2] * i1, of[dt][3] * i1);
    }
}

// ---------------------------------------------------------------------------
extern "C" void kernel_launch(void* const* d_in, const int* in_sizes, int n_in,
                              void* d_out, int out_size)
{
    (void)in_sizes; (void)n_in; (void)out_size;
    const float* x  = (const float*)d_in[0];
    const float* Wq = (const float*)d_in[1];
    const float* Wk = (const float*)d_in[2];
    const float* Wv = (const float*)d_in[3];
    const float* Wo = (const float*)d_in[4];
    float* out = (float*)d_out;

    const int M = BATCH * SQ;   // 4096

    cudaFuncSetAttribute(gemm_f16, cudaFuncAttributeMaxDynamicSharedMemorySize, GEMM_SMEM);
    cudaFuncSetAttribute(gqa_attn_tc, cudaFuncAttributeMaxDynamicSharedMemorySize, ATTN_SMEM);

    __half* xh; cudaGetSymbolAddress((void**)&xh, g_Xh);
    __half* wh; cudaGetSymbolAddress((void**)&wh, g_Wh);

    // Pre-convert x and all weights to fp16 in ONE launch
    cvt_all<<<(N4_TOTAL + 255) / 256, 256>>>(
        (const float4*)x, (const float4*)Wq, (const float4*)Wk,
        (const float4*)Wv, (const float4*)Wo, (__half2*)xh, (__half2*)wh);

    // Fused Q|K|V = x @ [Wq;Wk;Wv]^T  (Q scaled 0.125, V transposed)
    gemm_f16<<<dim3(3072 / 128, M / 128), 256, GEMM_SMEM>>>(0, 0, 4, nullptr, M, DM);
    // Causal GQA attention -> g_Ch
    gqa_attn_tc<<<dim3(SQ / 128, BATCH * NH), 256, ATTN_SMEM>>>();
    // out = ctx @ Wo^T  (fp32 output)
    gemm_f16<<<dim3(DM / 128, M / 128), 256, GEMM_SMEM>>>(1, WO_OFF, 3, out, M, DM);
}